// round 1
// baseline (speedup 1.0000x reference)
#include <cuda_runtime.h>
#include <math.h>

// Problem constants
#define B_SZ   512
#define N_SZ   256
#define N_ITERS 400
#define LAMBD  1.0f
#define KAPPA  0.1f

// Scratch: G1 = U^T U, G2 = A^T A per batch (134 MB each), per-batch step.
__device__ float g_G1[(size_t)B_SZ * N_SZ * N_SZ];
__device__ float g_G2[(size_t)B_SZ * N_SZ * N_SZ];
__device__ float g_step[B_SZ];

// ---------------------------------------------------------------------------
// Kernel 1: per-batch step size: step = 1/(lambd*||U||_F^2 + kappa*||A||_F + 1)
// grid = 512 blocks, 256 threads
// ---------------------------------------------------------------------------
__global__ __launch_bounds__(256) void step_kernel(const float* __restrict__ U,
                                                   const float* __restrict__ A) {
    const int b = blockIdx.x;
    const int t = threadIdx.x;
    const float* Ub = U + (size_t)b * (N_SZ * N_SZ);
    const float* Ab = A + (size_t)b * (N_SZ * N_SZ);

    float su = 0.f, sa = 0.f;
    #pragma unroll 4
    for (int idx = t; idx < N_SZ * N_SZ; idx += 256) {
        float u = Ub[idx]; su = fmaf(u, u, su);
        float a = Ab[idx]; sa = fmaf(a, a, sa);
    }
    __shared__ float rs_u[8], rs_a[8];
    #pragma unroll
    for (int o = 16; o; o >>= 1) {
        su += __shfl_xor_sync(0xFFFFFFFFu, su, o);
        sa += __shfl_xor_sync(0xFFFFFFFFu, sa, o);
    }
    if ((t & 31) == 0) { rs_u[t >> 5] = su; rs_a[t >> 5] = sa; }
    __syncthreads();
    if (t == 0) {
        float tu = 0.f, ta = 0.f;
        #pragma unroll
        for (int q = 0; q < 8; q++) { tu += rs_u[q]; ta += rs_a[q]; }
        g_step[b] = 1.0f / (LAMBD * tu + KAPPA * sqrtf(ta) + 1.0f);
    }
}

// ---------------------------------------------------------------------------
// Kernel 2: batched SYRK  G = X^T X  (full matrix stored).
// Block computes a 64x64 tile with 256 threads (4x4 microtiles), K-step 16.
// grid = (4, 4, 1024): z<512 -> U->G1, z>=512 -> A->G2
// ---------------------------------------------------------------------------
__global__ __launch_bounds__(256) void syrk_kernel(const float* __restrict__ U,
                                                   const float* __restrict__ A) {
    const int mat = blockIdx.z;
    const int b = mat & (B_SZ - 1);
    const bool isA = (mat >= B_SZ);
    const float* X = (isA ? A : U) + (size_t)b * (N_SZ * N_SZ);
    float* G = (isA ? g_G2 : g_G1) + (size_t)b * (N_SZ * N_SZ);

    const int jB = blockIdx.x * 64;
    const int kB = blockIdx.y * 64;

    __shared__ float Xa[16][64];
    __shared__ float Xb[16][64];

    const int tid = threadIdx.x;
    const int tx = tid & 15;
    const int ty = tid >> 4;

    float acc[4][4];
    #pragma unroll
    for (int a = 0; a < 4; a++)
        #pragma unroll
        for (int c = 0; c < 4; c++) acc[a][c] = 0.f;

    for (int i0 = 0; i0 < N_SZ; i0 += 16) {
        #pragma unroll
        for (int e = 0; e < 4; e++) {
            int l = e * 256 + tid;
            int r = l >> 6, c = l & 63;
            Xa[r][c] = X[(size_t)(i0 + r) * N_SZ + jB + c];
            Xb[r][c] = X[(size_t)(i0 + r) * N_SZ + kB + c];
        }
        __syncthreads();
        #pragma unroll
        for (int kk = 0; kk < 16; kk++) {
            float4 av = *(const float4*)&Xa[kk][ty * 4];
            float4 bv = *(const float4*)&Xb[kk][tx * 4];
            float ar[4] = {av.x, av.y, av.z, av.w};
            float br[4] = {bv.x, bv.y, bv.z, bv.w};
            #pragma unroll
            for (int a = 0; a < 4; a++)
                #pragma unroll
                for (int c = 0; c < 4; c++)
                    acc[a][c] = fmaf(ar[a], br[c], acc[a][c]);
        }
        __syncthreads();
    }
    #pragma unroll
    for (int a = 0; a < 4; a++) {
        float4 v = make_float4(acc[a][0], acc[a][1], acc[a][2], acc[a][3]);
        *(float4*)&G[(size_t)(jB + ty * 4 + a) * N_SZ + kB + tx * 4] = v;
    }
}

// ---------------------------------------------------------------------------
// Kernel 3: the 400-iteration PGD loop. One CTA per batch, 256 threads
// (thread t owns coordinate t). Matvecs read G column-wise (symmetric ->
// same as row) so consecutive threads hit consecutive addresses.
// ---------------------------------------------------------------------------
__global__ __launch_bounds__(256) void pgd_kernel(const float* __restrict__ mu,
                                                  float* __restrict__ out) {
    const int b = blockIdx.x;
    const int t = threadIdx.x;

    const float* __restrict__ G1b = g_G1 + (size_t)b * (N_SZ * N_SZ);
    const float* __restrict__ G2b = g_G2 + (size_t)b * (N_SZ * N_SZ);

    const float mu_i = mu[(size_t)b * N_SZ + t];
    const float step = g_step[b];

    __shared__ float w_s[N_SZ];
    __shared__ float v_s[N_SZ];
    __shared__ float s_s[N_SZ];   // sort buffer (descending)
    __shared__ float c_s[N_SZ];   // inclusive cumsum of sorted
    __shared__ float red_s[8];
    __shared__ float bc;

    w_s[t] = 1.0f / (float)N_SZ;
    __syncthreads();

    for (int it = 0; it < N_ITERS; it++) {
        // ---- matvecs: acc1 = (G1 w)_t, acc2 = (G2 w)_t (coalesced column read)
        float acc1 = 0.f, acc2 = 0.f;
        #pragma unroll 8
        for (int j = 0; j < N_SZ; j++) {
            float wj = w_s[j];
            acc1 = fmaf(__ldg(&G1b[(j << 8) + t]), wj, acc1);
            acc2 = fmaf(__ldg(&G2b[(j << 8) + t]), wj, acc2);
        }

        // ---- nrm = sqrt(max(w . G2w, 1e-12))
        float p = w_s[t] * acc2;
        #pragma unroll
        for (int o = 16; o; o >>= 1) p += __shfl_xor_sync(0xFFFFFFFFu, p, o);
        if ((t & 31) == 0) red_s[t >> 5] = p;
        __syncthreads();
        if (t == 0) {
            float d = 0.f;
            #pragma unroll
            for (int q = 0; q < 8; q++) d += red_s[q];
            bc = sqrtf(fmaxf(d, 1e-12f));
        }
        __syncthreads();
        const float nrm = bc;

        // ---- gradient step
        float grad = -mu_i + LAMBD * acc1 + KAPPA * acc2 / nrm;
        float v = w_s[t] - step * grad;
        v_s[t] = v;
        s_s[t] = v;
        __syncthreads();

        // ---- bitonic sort DESCENDING (256 elems, 36 compare-exchange steps)
        #pragma unroll
        for (int k = 2; k <= N_SZ; k <<= 1) {
            for (int j = k >> 1; j > 0; j >>= 1) {
                int ixj = t ^ j;
                if (ixj > t) {
                    float x = s_s[t], y = s_s[ixj];
                    bool desc = ((t & k) == 0);
                    if (desc ? (x < y) : (x > y)) { s_s[t] = y; s_s[ixj] = x; }
                }
                __syncthreads();
            }
        }

        // ---- inclusive cumsum (Hillis-Steele)
        c_s[t] = s_s[t];
        __syncthreads();
        #pragma unroll
        for (int off = 1; off < N_SZ; off <<= 1) {
            float add = (t >= off) ? c_s[t - off] : 0.f;
            __syncthreads();
            c_s[t] += add;
            __syncthreads();
        }

        // ---- rho = #{ u_i + (1 - css_i)/(i+1) > 0 }, tau = (css[rho-1]-1)/rho
        int cond = (s_s[t] + (1.0f - c_s[t]) / (float)(t + 1) > 0.f) ? 1 : 0;
        #pragma unroll
        for (int o = 16; o; o >>= 1) cond += __shfl_xor_sync(0xFFFFFFFFu, cond, o);
        if ((t & 31) == 0) red_s[t >> 5] = (float)cond;
        __syncthreads();
        if (t == 0) {
            int rho = 0;
            #pragma unroll
            for (int q = 0; q < 8; q++) rho += (int)red_s[q];
            bc = (c_s[rho - 1] - 1.0f) / (float)rho;
        }
        __syncthreads();
        const float tau = bc;

        float wn = fmaxf(v_s[t] - tau, 0.f);
        __syncthreads();
        w_s[t] = wn;
        __syncthreads();
    }

    // ---- final clamp + renormalize
    float w = fmaxf(w_s[t], 0.f);
    float s = w;
    #pragma unroll
    for (int o = 16; o; o >>= 1) s += __shfl_xor_sync(0xFFFFFFFFu, s, o);
    if ((t & 31) == 0) red_s[t >> 5] = s;
    __syncthreads();
    if (t == 0) {
        float tot = 0.f;
        #pragma unroll
        for (int q = 0; q < 8; q++) tot += red_s[q];
        bc = tot;
    }
    __syncthreads();
    out[(size_t)b * N_SZ + t] = w / (bc + 1e-12f);
}

// ---------------------------------------------------------------------------
// Launcher
// inputs: d_in[0]=mu [512,256] f32, d_in[1]=U [512,256,256] f32,
//         d_in[2]=A [512,256,256] f32 ; out: w [512,256] f32
// ---------------------------------------------------------------------------
extern "C" void kernel_launch(void* const* d_in, const int* in_sizes, int n_in,
                              void* d_out, int out_size) {
    const float* mu = (const float*)d_in[0];
    const float* U  = (const float*)d_in[1];
    const float* A  = (const float*)d_in[2];
    float* out = (float*)d_out;

    step_kernel<<<B_SZ, 256>>>(U, A);

    dim3 gsyrk(N_SZ / 64, N_SZ / 64, 2 * B_SZ);
    syrk_kernel<<<gsyrk, 256>>>(U, A);

    pgd_kernel<<<B_SZ, 256>>>(mu, out);
}

// round 2
// speedup vs baseline: 1.9692x; 1.9692x over previous
#include <cuda_runtime.h>
#include <math.h>

// Problem constants
#define B_SZ   512
#define N_SZ   256
#define N_ITERS 400
#define LAMBD  1.0f
#define KAPPA  0.1f

// Scratch: G1 = U^T U, G2 = A^T A per batch, per-batch step.
__device__ float g_G1[(size_t)B_SZ * N_SZ * N_SZ];
__device__ float g_G2[(size_t)B_SZ * N_SZ * N_SZ];
__device__ float g_step[B_SZ];

// ---------------------------------------------------------------------------
// Kernel 1: per-batch step size: step = 1/(lambd*||U||_F^2 + kappa*||A||_F + 1)
// ---------------------------------------------------------------------------
__global__ __launch_bounds__(256) void step_kernel(const float* __restrict__ U,
                                                   const float* __restrict__ A) {
    const int b = blockIdx.x;
    const int t = threadIdx.x;
    const float* Ub = U + (size_t)b * (N_SZ * N_SZ);
    const float* Ab = A + (size_t)b * (N_SZ * N_SZ);

    float su = 0.f, sa = 0.f;
    #pragma unroll 4
    for (int idx = t; idx < N_SZ * N_SZ; idx += 256) {
        float u = Ub[idx]; su = fmaf(u, u, su);
        float a = Ab[idx]; sa = fmaf(a, a, sa);
    }
    __shared__ float rs_u[8], rs_a[8];
    #pragma unroll
    for (int o = 16; o; o >>= 1) {
        su += __shfl_xor_sync(0xFFFFFFFFu, su, o);
        sa += __shfl_xor_sync(0xFFFFFFFFu, sa, o);
    }
    if ((t & 31) == 0) { rs_u[t >> 5] = su; rs_a[t >> 5] = sa; }
    __syncthreads();
    if (t == 0) {
        float tu = 0.f, ta = 0.f;
        #pragma unroll
        for (int q = 0; q < 8; q++) { tu += rs_u[q]; ta += rs_a[q]; }
        g_step[b] = 1.0f / (LAMBD * tu + KAPPA * sqrtf(ta) + 1.0f);
    }
}

// ---------------------------------------------------------------------------
// Kernel 2: batched SYRK  G = X^T X, computing only upper-triangle 64x64
// tile-pairs (10 of 16) and mirror-writing the transpose block.
// grid = (10, 1, 1024): z<512 -> U->G1, z>=512 -> A->G2. 256 threads.
// ---------------------------------------------------------------------------
__global__ __launch_bounds__(256) void syrk_kernel(const float* __restrict__ U,
                                                   const float* __restrict__ A) {
    const int mat = blockIdx.z;
    const int b = mat & (B_SZ - 1);
    const bool isA = (mat >= B_SZ);
    const float* X = (isA ? A : U) + (size_t)b * (N_SZ * N_SZ);
    float* G = (isA ? g_G2 : g_G1) + (size_t)b * (N_SZ * N_SZ);

    // decode linear tile-pair index m (0..9) -> (tj, tk), tj <= tk
    const int m = blockIdx.x;
    int tj, tk;
    if (m < 4)      { tj = 0; tk = m; }
    else if (m < 7) { tj = 1; tk = m - 3; }
    else if (m < 9) { tj = 2; tk = m - 5; }
    else            { tj = 3; tk = 3; }
    const int jB = tj * 64;
    const int kB = tk * 64;

    __shared__ float Xa[16][64];
    __shared__ float Xb[16][64];

    const int tid = threadIdx.x;
    const int tx = tid & 15;
    const int ty = tid >> 4;

    float acc[4][4];
    #pragma unroll
    for (int a = 0; a < 4; a++)
        #pragma unroll
        for (int c = 0; c < 4; c++) acc[a][c] = 0.f;

    for (int i0 = 0; i0 < N_SZ; i0 += 16) {
        #pragma unroll
        for (int e = 0; e < 4; e++) {
            int l = e * 256 + tid;
            int r = l >> 6, c = l & 63;
            Xa[r][c] = X[(size_t)(i0 + r) * N_SZ + jB + c];
            Xb[r][c] = X[(size_t)(i0 + r) * N_SZ + kB + c];
        }
        __syncthreads();
        #pragma unroll
        for (int kk = 0; kk < 16; kk++) {
            float4 av = *(const float4*)&Xa[kk][ty * 4];
            float4 bv = *(const float4*)&Xb[kk][tx * 4];
            float ar[4] = {av.x, av.y, av.z, av.w};
            float br[4] = {bv.x, bv.y, bv.z, bv.w};
            #pragma unroll
            for (int a = 0; a < 4; a++)
                #pragma unroll
                for (int c = 0; c < 4; c++)
                    acc[a][c] = fmaf(ar[a], br[c], acc[a][c]);
        }
        __syncthreads();
    }
    // coalesced store of (tj,tk) block
    #pragma unroll
    for (int a = 0; a < 4; a++) {
        float4 v = make_float4(acc[a][0], acc[a][1], acc[a][2], acc[a][3]);
        *(float4*)&G[(size_t)(jB + ty * 4 + a) * N_SZ + kB + tx * 4] = v;
    }
    // mirror store of (tk,tj) block (scalar, small one-time cost)
    if (jB != kB) {
        #pragma unroll
        for (int a = 0; a < 4; a++)
            #pragma unroll
            for (int c = 0; c < 4; c++)
                G[(size_t)(kB + tx * 4 + c) * N_SZ + jB + ty * 4 + a] = acc[a][c];
    }
}

// ---------------------------------------------------------------------------
// Kernel 3: 400-iteration PGD. 512 threads/CTA, one CTA per batch.
// Thread t: coordinate i = t&255, j-half h = t>>8. Matvecs coalesced.
// Projection: single-warp Newton root-find for tau (no sort, no scan).
// 2 barriers per iteration.
// ---------------------------------------------------------------------------
__global__ __launch_bounds__(512, 4) void pgd_kernel(const float* __restrict__ mu,
                                                     float* __restrict__ out) {
    const int b = blockIdx.x;
    const int t = threadIdx.x;
    const int i = t & 255;
    const int h = t >> 8;

    const float* __restrict__ G1b = g_G1 + (size_t)b * (N_SZ * N_SZ);
    const float* __restrict__ G2b = g_G2 + (size_t)b * (N_SZ * N_SZ);

    __shared__ float w_s[N_SZ];
    __shared__ float mu_s[N_SZ];
    __shared__ float p1[2][N_SZ];
    __shared__ float p2[2][N_SZ];
    __shared__ float tot_s;

    if (t < N_SZ) {
        w_s[t] = 1.0f / (float)N_SZ;
        mu_s[t] = mu[(size_t)b * N_SZ + t];
    }
    __syncthreads();

    const float* __restrict__ G1p = G1b + ((size_t)h << 15) + i;  // h*128*256 + i
    const float* __restrict__ G2p = G2b + ((size_t)h << 15) + i;
    const float step = g_step[b];

    for (int it = 0; it < N_ITERS; it++) {
        // ---- matvec partials over j in [128h, 128h+128), coalesced in i
        float acc1 = 0.f, acc2 = 0.f;
        const float* wp = &w_s[h << 7];
        #pragma unroll 4
        for (int j = 0; j < 128; j++) {
            float wj = wp[j];
            acc1 = fmaf(__ldg(G1p + ((size_t)j << 8)), wj, acc1);
            acc2 = fmaf(__ldg(G2p + ((size_t)j << 8)), wj, acc2);
        }
        p1[h][i] = acc1;
        p2[h][i] = acc2;
        __syncthreads();

        // ---- warp 0: nrm, gradient step, Newton projection, w update
        if (t < 32) {
            // pass 1: prod = w . (G2 w)
            float prod = 0.f;
            #pragma unroll
            for (int k = 0; k < 8; k++) {
                int c = t + (k << 5);
                float g2v = p2[0][c] + p2[1][c];
                prod = fmaf(w_s[c], g2v, prod);
            }
            #pragma unroll
            for (int o = 16; o; o >>= 1) prod += __shfl_xor_sync(0xFFFFFFFFu, prod, o);
            const float nrm = sqrtf(fmaxf(prod, 1e-12f));
            const float kin = KAPPA / nrm;

            // pass 2: v = w - step * grad ; S = sum(v)
            float v[8];
            float S = 0.f;
            #pragma unroll
            for (int k = 0; k < 8; k++) {
                int c = t + (k << 5);
                float g1v = p1[0][c] + p1[1][c];
                float g2v = p2[0][c] + p2[1][c];
                float grad = -mu_s[c] + LAMBD * g1v + kin * g2v;
                v[k] = w_s[c] - step * grad;
                S += v[k];
            }
            #pragma unroll
            for (int o = 16; o; o >>= 1) S += __shfl_xor_sync(0xFFFFFFFFu, S, o);

            // Newton on f(tau) = sum(relu(v - tau)) - 1 (convex, pw-linear,
            // tau0 <= tau*, monotone convergence, exact at the root)
            float tau = (S - 1.0f) * (1.0f / (float)N_SZ);
            for (int nit = 0; nit < 64; nit++) {
                float s = 0.f, cnt = 0.f;
                #pragma unroll
                for (int k = 0; k < 8; k++) {
                    float d = v[k] - tau;
                    if (d > 0.f) { s += d; cnt += 1.0f; }
                }
                #pragma unroll
                for (int o = 16; o; o >>= 1) {
                    s   += __shfl_xor_sync(0xFFFFFFFFu, s, o);
                    cnt += __shfl_xor_sync(0xFFFFFFFFu, cnt, o);
                }
                if (cnt < 0.5f) break;
                float delta = (s - 1.0f) / cnt;
                tau += delta;
                if (delta <= 0.0f) break;
            }

            #pragma unroll
            for (int k = 0; k < 8; k++)
                w_s[t + (k << 5)] = fmaxf(v[k] - tau, 0.f);
        }
        __syncthreads();
    }

    // ---- final clamp + renormalize
    if (t < 32) {
        float sloc = 0.f;
        #pragma unroll
        for (int k = 0; k < 8; k++) sloc += fmaxf(w_s[t + (k << 5)], 0.f);
        #pragma unroll
        for (int o = 16; o; o >>= 1) sloc += __shfl_xor_sync(0xFFFFFFFFu, sloc, o);
        if (t == 0) tot_s = sloc;
    }
    __syncthreads();
    if (t < N_SZ)
        out[(size_t)b * N_SZ + t] = fmaxf(w_s[t], 0.f) / (tot_s + 1e-12f);
}

// ---------------------------------------------------------------------------
// Launcher
// inputs: d_in[0]=mu [512,256] f32, d_in[1]=U [512,256,256] f32,
//         d_in[2]=A [512,256,256] f32 ; out: w [512,256] f32
// ---------------------------------------------------------------------------
extern "C" void kernel_launch(void* const* d_in, const int* in_sizes, int n_in,
                              void* d_out, int out_size) {
    const float* mu = (const float*)d_in[0];
    const float* U  = (const float*)d_in[1];
    const float* A  = (const float*)d_in[2];
    float* out = (float*)d_out;

    step_kernel<<<B_SZ, 256>>>(U, A);

    dim3 gsyrk(10, 1, 2 * B_SZ);
    syrk_kernel<<<gsyrk, 256>>>(U, A);

    pgd_kernel<<<B_SZ, 512>>>(mu, out);
}

// round 3
// speedup vs baseline: 6.0439x; 3.0693x over previous
#include <cuda_runtime.h>
#include <cuda_fp16.h>
#include <math.h>

// Problem constants
#define B_SZ    512
#define N_SZ    256
#define N_ITERS 400
#define LAMBD   1.0f
#define KAPPA   0.1f

// 32x32 tiles over the 8x8 tile-grid upper triangle: 36 tiles.
#define NTILES   36
#define TILE_W   33              // padded row stride (conflict-free both orientations)
#define TILE_ELEMS (32 * TILE_W) // 1056

// Scratch: G1 = U^T U, G2 = A^T A (full, fp32) per batch; per-batch step.
__device__ float g_G1[(size_t)B_SZ * N_SZ * N_SZ];
__device__ float g_G2[(size_t)B_SZ * N_SZ * N_SZ];
__device__ float g_step[B_SZ];

// tile index decode tables: tix -> (a, b), a <= b, lexicographic
__constant__ int c_TA[NTILES] = {0,0,0,0,0,0,0,0, 1,1,1,1,1,1,1, 2,2,2,2,2,2,
                                 3,3,3,3,3, 4,4,4,4, 5,5,5, 6,6, 7};
__constant__ int c_TB[NTILES] = {0,1,2,3,4,5,6,7, 1,2,3,4,5,6,7, 2,3,4,5,6,7,
                                 3,4,5,6,7, 4,5,6,7, 5,6,7, 6,7, 7};

__device__ __forceinline__ int tri_idx(int a, int b) {  // a <= b
    return a * 8 - (a * (a - 1)) / 2 + (b - a);
}

// ---------------------------------------------------------------------------
// Kernel 1: per-batch step size
// ---------------------------------------------------------------------------
__global__ __launch_bounds__(256) void step_kernel(const float* __restrict__ U,
                                                   const float* __restrict__ A) {
    const int b = blockIdx.x;
    const int t = threadIdx.x;
    const float* Ub = U + (size_t)b * (N_SZ * N_SZ);
    const float* Ab = A + (size_t)b * (N_SZ * N_SZ);

    float su = 0.f, sa = 0.f;
    #pragma unroll 4
    for (int idx = t; idx < N_SZ * N_SZ; idx += 256) {
        float u = Ub[idx]; su = fmaf(u, u, su);
        float a = Ab[idx]; sa = fmaf(a, a, sa);
    }
    __shared__ float rs_u[8], rs_a[8];
    #pragma unroll
    for (int o = 16; o; o >>= 1) {
        su += __shfl_xor_sync(0xFFFFFFFFu, su, o);
        sa += __shfl_xor_sync(0xFFFFFFFFu, sa, o);
    }
    if ((t & 31) == 0) { rs_u[t >> 5] = su; rs_a[t >> 5] = sa; }
    __syncthreads();
    if (t == 0) {
        float tu = 0.f, ta = 0.f;
        #pragma unroll
        for (int q = 0; q < 8; q++) { tu += rs_u[q]; ta += rs_a[q]; }
        g_step[b] = 1.0f / (LAMBD * tu + KAPPA * sqrtf(ta) + 1.0f);
    }
}

// ---------------------------------------------------------------------------
// Kernel 2: batched SYRK  G = X^T X, upper-triangle 64x64 tile-pairs,
// mirror-writes the transpose block so the full matrix exists in global.
// ---------------------------------------------------------------------------
__global__ __launch_bounds__(256) void syrk_kernel(const float* __restrict__ U,
                                                   const float* __restrict__ A) {
    const int mat = blockIdx.z;
    const int b = mat & (B_SZ - 1);
    const bool isA = (mat >= B_SZ);
    const float* X = (isA ? A : U) + (size_t)b * (N_SZ * N_SZ);
    float* G = (isA ? g_G2 : g_G1) + (size_t)b * (N_SZ * N_SZ);

    const int m = blockIdx.x;
    int tj, tk;
    if (m < 4)      { tj = 0; tk = m; }
    else if (m < 7) { tj = 1; tk = m - 3; }
    else if (m < 9) { tj = 2; tk = m - 5; }
    else            { tj = 3; tk = 3; }
    const int jB = tj * 64;
    const int kB = tk * 64;

    __shared__ float Xa[16][64];
    __shared__ float Xb[16][64];

    const int tid = threadIdx.x;
    const int tx = tid & 15;
    const int ty = tid >> 4;

    float acc[4][4];
    #pragma unroll
    for (int a = 0; a < 4; a++)
        #pragma unroll
        for (int c = 0; c < 4; c++) acc[a][c] = 0.f;

    for (int i0 = 0; i0 < N_SZ; i0 += 16) {
        #pragma unroll
        for (int e = 0; e < 4; e++) {
            int l = e * 256 + tid;
            int r = l >> 6, c = l & 63;
            Xa[r][c] = X[(size_t)(i0 + r) * N_SZ + jB + c];
            Xb[r][c] = X[(size_t)(i0 + r) * N_SZ + kB + c];
        }
        __syncthreads();
        #pragma unroll
        for (int kk = 0; kk < 16; kk++) {
            float4 av = *(const float4*)&Xa[kk][ty * 4];
            float4 bv = *(const float4*)&Xb[kk][tx * 4];
            float ar[4] = {av.x, av.y, av.z, av.w};
            float br[4] = {bv.x, bv.y, bv.z, bv.w};
            #pragma unroll
            for (int a = 0; a < 4; a++)
                #pragma unroll
                for (int c = 0; c < 4; c++)
                    acc[a][c] = fmaf(ar[a], br[c], acc[a][c]);
        }
        __syncthreads();
    }
    #pragma unroll
    for (int a = 0; a < 4; a++) {
        float4 v = make_float4(acc[a][0], acc[a][1], acc[a][2], acc[a][3]);
        *(float4*)&G[(size_t)(jB + ty * 4 + a) * N_SZ + kB + tx * 4] = v;
    }
    if (jB != kB) {
        #pragma unroll
        for (int a = 0; a < 4; a++)
            #pragma unroll
            for (int c = 0; c < 4; c++)
                G[(size_t)(kB + tx * 4 + c) * N_SZ + jB + ty * 4 + a] = acc[a][c];
    }
}

// ---------------------------------------------------------------------------
// Kernel 3: 400-iteration PGD fully from SMEM.
// Triangles resident in shared memory: G1 fp32, G2 fp16.
// 16 warps = (8 output bands) x (2 halves of the j-range).
// Symmetric matvec: tile (a,b), a<=b stored once; band-r warp reads it in
// row orientation when r==a (lane-stride TILE_W) or column orientation when
// r==b (contiguous). Both conflict-free.
// ---------------------------------------------------------------------------
__global__ __launch_bounds__(512, 1) void pgd_kernel(const float* __restrict__ mu,
                                                     float* __restrict__ out) {
    extern __shared__ unsigned char smem_raw[];
    float* sm_g1 = (float*)smem_raw;                              // 36*1056*4 = 152064
    __half* sm_g2 = (__half*)(smem_raw + NTILES * TILE_ELEMS * 4); // +76032 = 228096
    float* sm_w  = (float*)(smem_raw + 228096);                   // 1 KB
    float* sm_y1 = sm_w + 256;                                    // 1 KB (also reused for v)
    float* sm_y2 = sm_y1 + 256;                                   // 1 KB
    float* sm_sc = sm_y2 + 256;                                   // scalars

    const int b = blockIdx.x;
    const int t = threadIdx.x;
    const int lane = t & 31;
    const int wrp = t >> 5;
    const int r = wrp & 7;      // output band
    const int h = wrp >> 3;     // j-half

    const float* __restrict__ G1g = g_G1 + (size_t)b * (N_SZ * N_SZ);
    const float* __restrict__ G2g = g_G2 + (size_t)b * (N_SZ * N_SZ);

    // ---- load triangles into smem (G2 converted to fp16) ----
    for (int tix = 0; tix < NTILES; tix++) {
        const int a0 = c_TA[tix], b0 = c_TB[tix];
        #pragma unroll
        for (int e = 0; e < 2; e++) {
            int idx = t + e * 512;           // 0..1023
            int i = idx >> 5, j = idx & 31;
            size_t g = (size_t)(a0 * 32 + i) * N_SZ + b0 * 32 + j;
            sm_g1[tix * TILE_ELEMS + i * TILE_W + j] = G1g[g];
            sm_g2[tix * TILE_ELEMS + i * TILE_W + j] = __float2half(G2g[g]);
        }
    }

    // per-thread init
    if (t < N_SZ) sm_w[t] = 1.0f / (float)N_SZ;
    const float step = g_step[b];

    // warp 0 preloads mu for its 8 coords (c = lane + 32k)
    float mu_r[8];
    if (wrp == 0) {
        #pragma unroll
        for (int k = 0; k < 8; k++)
            mu_r[k] = mu[(size_t)b * N_SZ + lane + (k << 5)];
    }
    __syncthreads();

    for (int it = 0; it < N_ITERS; it++) {
        // ---- symmetric fused matvec partials: band r, j in [128h,128h+128)
        float acc1 = 0.f, acc2 = 0.f;
        #pragma unroll
        for (int bb = 0; bb < 4; bb++) {
            const int bband = (h << 2) + bb;
            const bool rowor = (bband >= r);
            const int a0 = rowor ? r : bband;
            const int b0 = rowor ? bband : r;
            const int tix = tri_idx(a0, b0);
            const float* __restrict__ T1 = sm_g1 + tix * TILE_ELEMS;
            const __half* __restrict__ T2 = sm_g2 + tix * TILE_ELEMS;
            const float* __restrict__ wb = sm_w + (bband << 5);
            const int stI = rowor ? TILE_W : 1;  // lane stride
            const int stJ = rowor ? 1 : TILE_W;  // step stride
            int ofs = lane * stI;
            #pragma unroll
            for (int j = 0; j < 32; j++) {
                float wv = wb[j];
                acc1 = fmaf(T1[ofs], wv, acc1);
                acc2 = fmaf(__half2float(T2[ofs]), wv, acc2);
                ofs += stJ;
            }
        }
        const int c0 = (r << 5) + lane;
        if (h == 0) { sm_y1[c0] = acc1; sm_y2[c0] = acc2; }
        __syncthreads();
        if (h == 1) { sm_y1[c0] += acc1; sm_y2[c0] += acc2; }
        __syncthreads();

        // ---- warp 0: nrm, gradient step, Newton simplex projection
        if (wrp == 0) {
            float wv[8], y2v[8];
            float prod = 0.f;
            #pragma unroll
            for (int k = 0; k < 8; k++) {
                int c = lane + (k << 5);
                wv[k] = sm_w[c];
                y2v[k] = sm_y2[c];
                prod = fmaf(wv[k], y2v[k], prod);
            }
            #pragma unroll
            for (int o = 16; o; o >>= 1) prod += __shfl_xor_sync(0xFFFFFFFFu, prod, o);
            const float nrm = sqrtf(fmaxf(prod, 1e-12f));
            const float kin = KAPPA / nrm;

            float v[8], S = 0.f;
            #pragma unroll
            for (int k = 0; k < 8; k++) {
                int c = lane + (k << 5);
                float grad = -mu_r[k] + LAMBD * sm_y1[c] + kin * y2v[k];
                v[k] = wv[k] - step * grad;
                S += v[k];
            }
            #pragma unroll
            for (int o = 16; o; o >>= 1) S += __shfl_xor_sync(0xFFFFFFFFu, S, o);

            // Newton on f(tau) = sum(relu(v - tau)) - 1: tau0 <= tau*,
            // monotone from below, exact at the root.
            float tau = (S - 1.0f) * (1.0f / (float)N_SZ);
            for (int nit = 0; nit < 64; nit++) {
                float s = 0.f, cnt = 0.f;
                #pragma unroll
                for (int k = 0; k < 8; k++) {
                    float d = v[k] - tau;
                    if (d > 0.f) { s += d; cnt += 1.0f; }
                }
                #pragma unroll
                for (int o = 16; o; o >>= 1) {
                    s   += __shfl_xor_sync(0xFFFFFFFFu, s, o);
                    cnt += __shfl_xor_sync(0xFFFFFFFFu, cnt, o);
                }
                if (cnt < 0.5f) break;
                float delta = (s - 1.0f) / cnt;
                tau += delta;
                if (delta <= 0.0f) break;
            }

            #pragma unroll
            for (int k = 0; k < 8; k++)
                sm_w[lane + (k << 5)] = fmaxf(v[k] - tau, 0.f);
        }
        __syncthreads();
    }

    // ---- final clamp + renormalize
    if (wrp == 0) {
        float sloc = 0.f;
        #pragma unroll
        for (int k = 0; k < 8; k++) sloc += fmaxf(sm_w[lane + (k << 5)], 0.f);
        #pragma unroll
        for (int o = 16; o; o >>= 1) sloc += __shfl_xor_sync(0xFFFFFFFFu, sloc, o);
        if (lane == 0) sm_sc[0] = sloc;
    }
    __syncthreads();
    if (t < N_SZ)
        out[(size_t)b * N_SZ + t] = fmaxf(sm_w[t], 0.f) / (sm_sc[0] + 1e-12f);
}

// ---------------------------------------------------------------------------
// Launcher
// ---------------------------------------------------------------------------
#define PGD_SMEM (NTILES * TILE_ELEMS * 4 + NTILES * TILE_ELEMS * 2 + 3 * 256 * 4 + 16)

extern "C" void kernel_launch(void* const* d_in, const int* in_sizes, int n_in,
                              void* d_out, int out_size) {
    const float* mu = (const float*)d_in[0];
    const float* U  = (const float*)d_in[1];
    const float* A  = (const float*)d_in[2];
    float* out = (float*)d_out;

    // raise the dynamic smem limit for the PGD kernel (idempotent host call)
    cudaFuncSetAttribute(pgd_kernel, cudaFuncAttributeMaxDynamicSharedMemorySize,
                         PGD_SMEM);

    step_kernel<<<B_SZ, 256>>>(U, A);

    dim3 gsyrk(10, 1, 2 * B_SZ);
    syrk_kernel<<<gsyrk, 256>>>(U, A);

    pgd_kernel<<<B_SZ, 512, PGD_SMEM>>>(mu, out);
}

// round 5
// speedup vs baseline: 7.5432x; 1.2481x over previous
#include <cuda_runtime.h>
#include <cuda_fp16.h>
#include <math.h>
#include <stdint.h>

// Problem constants
#define B_SZ    512
#define N_SZ    256
#define N_ITERS 400
#define LAMBD   1.0f
#define KAPPA   0.1f

// Scratch: G1 = U^T U, G2 = A^T A (full, fp32) per batch; per-batch step.
__device__ float g_G1[(size_t)B_SZ * N_SZ * N_SZ];
__device__ float g_G2[(size_t)B_SZ * N_SZ * N_SZ];
__device__ float g_step[B_SZ];

// 32x32 tiles over the 8x8 tile-grid upper triangle: 36 tiles per matrix.
#define NTILES 36
__constant__ int c_TA[NTILES] = {0,0,0,0,0,0,0,0, 1,1,1,1,1,1,1, 2,2,2,2,2,2,
                                 3,3,3,3,3, 4,4,4,4, 5,5,5, 6,6, 7};
__constant__ int c_TB[NTILES] = {0,1,2,3,4,5,6,7, 1,2,3,4,5,6,7, 2,3,4,5,6,7,
                                 3,4,5,6,7, 4,5,6,7, 5,6,7, 6,7, 7};

__device__ __forceinline__ int tri_idx(int a, int b) {  // a <= b
    return a * 8 - (a * (a - 1)) / 2 + (b - a);
}

// SMEM layout for the PGD kernel.
// Tile: 32 rows x 40 halves (80B stride; rows 0..7 hit disjoint 16B bank
// segments: r*80 mod 128 = {0,80,32,112,64,16,96,48} -> ldmatrix conflict-free)
#define TILE_STRIDE_B 80
#define TILE_BYTES    (32 * TILE_STRIDE_B)      // 2560
#define MAT_BYTES     (NTILES * TILE_BYTES)     // 92160
#define SM_W     0                               // 256 fp16 (512 B)
#define SM_Y1    512                             // 256 f32
#define SM_Y2    1536                            // 256 f32
#define SM_TILES 4096
#define SM_TOTAL (SM_TILES + 2 * MAT_BYTES)      // 188416

// ---------------------------------------------------------------------------
// PTX helpers (base-PTX only: ldmatrix + mma.sync; NO tcgen05 / 'a'-gated ops)
// ---------------------------------------------------------------------------
__device__ __forceinline__ uint32_t smem_u32(const void* p) {
    uint32_t a;
    asm("{ .reg .u64 t; cvta.to.shared.u64 t, %1; cvt.u32.u64 %0, t; }"
        : "=r"(a) : "l"(p));
    return a;
}

__device__ __forceinline__ void ldsm4(uint32_t& a0, uint32_t& a1, uint32_t& a2,
                                      uint32_t& a3, uint32_t addr) {
    asm volatile("ldmatrix.sync.aligned.m8n8.x4.shared.b16 {%0,%1,%2,%3}, [%4];"
                 : "=r"(a0), "=r"(a1), "=r"(a2), "=r"(a3) : "r"(addr));
}
__device__ __forceinline__ void ldsm4t(uint32_t& a0, uint32_t& a1, uint32_t& a2,
                                       uint32_t& a3, uint32_t addr) {
    asm volatile("ldmatrix.sync.aligned.m8n8.x4.trans.shared.b16 {%0,%1,%2,%3}, [%4];"
                 : "=r"(a0), "=r"(a1), "=r"(a2), "=r"(a3) : "r"(addr));
}
__device__ __forceinline__ void mma16816(float* c, uint32_t a0, uint32_t a1,
                                         uint32_t a2, uint32_t a3,
                                         uint32_t b0, uint32_t b1) {
    asm volatile(
        "mma.sync.aligned.m16n8k16.row.col.f32.f16.f16.f32 "
        "{%0,%1,%2,%3}, {%4,%5,%6,%7}, {%8,%9}, {%0,%1,%2,%3};"
        : "+f"(c[0]), "+f"(c[1]), "+f"(c[2]), "+f"(c[3])
        : "r"(a0), "r"(a1), "r"(a2), "r"(a3), "r"(b0), "r"(b1));
}

// ---------------------------------------------------------------------------
// Kernel 1: per-batch step size
// ---------------------------------------------------------------------------
__global__ __launch_bounds__(256) void step_kernel(const float* __restrict__ U,
                                                   const float* __restrict__ A) {
    const int b = blockIdx.x;
    const int t = threadIdx.x;
    const float* Ub = U + (size_t)b * (N_SZ * N_SZ);
    const float* Ab = A + (size_t)b * (N_SZ * N_SZ);

    float su = 0.f, sa = 0.f;
    #pragma unroll 4
    for (int idx = t; idx < N_SZ * N_SZ; idx += 256) {
        float u = Ub[idx]; su = fmaf(u, u, su);
        float a = Ab[idx]; sa = fmaf(a, a, sa);
    }
    __shared__ float rs_u[8], rs_a[8];
    #pragma unroll
    for (int o = 16; o; o >>= 1) {
        su += __shfl_xor_sync(0xFFFFFFFFu, su, o);
        sa += __shfl_xor_sync(0xFFFFFFFFu, sa, o);
    }
    if ((t & 31) == 0) { rs_u[t >> 5] = su; rs_a[t >> 5] = sa; }
    __syncthreads();
    if (t == 0) {
        float tu = 0.f, ta = 0.f;
        #pragma unroll
        for (int q = 0; q < 8; q++) { tu += rs_u[q]; ta += rs_a[q]; }
        g_step[b] = 1.0f / (LAMBD * tu + KAPPA * sqrtf(ta) + 1.0f);
    }
}

// ---------------------------------------------------------------------------
// Kernel 2: batched SYRK G = X^T X (upper-triangle tile-pairs + mirror)
// ---------------------------------------------------------------------------
__global__ __launch_bounds__(256) void syrk_kernel(const float* __restrict__ U,
                                                   const float* __restrict__ A) {
    const int mat = blockIdx.z;
    const int b = mat & (B_SZ - 1);
    const bool isA = (mat >= B_SZ);
    const float* X = (isA ? A : U) + (size_t)b * (N_SZ * N_SZ);
    float* G = (isA ? g_G2 : g_G1) + (size_t)b * (N_SZ * N_SZ);

    const int m = blockIdx.x;
    int tj, tk;
    if (m < 4)      { tj = 0; tk = m; }
    else if (m < 7) { tj = 1; tk = m - 3; }
    else if (m < 9) { tj = 2; tk = m - 5; }
    else            { tj = 3; tk = 3; }
    const int jB = tj * 64;
    const int kB = tk * 64;

    __shared__ float Xa[16][64];
    __shared__ float Xb[16][64];

    const int tid = threadIdx.x;
    const int tx = tid & 15;
    const int ty = tid >> 4;

    float acc[4][4];
    #pragma unroll
    for (int a = 0; a < 4; a++)
        #pragma unroll
        for (int c = 0; c < 4; c++) acc[a][c] = 0.f;

    for (int i0 = 0; i0 < N_SZ; i0 += 16) {
        #pragma unroll
        for (int e = 0; e < 4; e++) {
            int l = e * 256 + tid;
            int r = l >> 6, c = l & 63;
            Xa[r][c] = X[(size_t)(i0 + r) * N_SZ + jB + c];
            Xb[r][c] = X[(size_t)(i0 + r) * N_SZ + kB + c];
        }
        __syncthreads();
        #pragma unroll
        for (int kk = 0; kk < 16; kk++) {
            float4 av = *(const float4*)&Xa[kk][ty * 4];
            float4 bv = *(const float4*)&Xb[kk][tx * 4];
            float ar[4] = {av.x, av.y, av.z, av.w};
            float br[4] = {bv.x, bv.y, bv.z, bv.w};
            #pragma unroll
            for (int a = 0; a < 4; a++)
                #pragma unroll
                for (int c = 0; c < 4; c++)
                    acc[a][c] = fmaf(ar[a], br[c], acc[a][c]);
        }
        __syncthreads();
    }
    #pragma unroll
    for (int a = 0; a < 4; a++) {
        float4 v = make_float4(acc[a][0], acc[a][1], acc[a][2], acc[a][3]);
        *(float4*)&G[(size_t)(jB + ty * 4 + a) * N_SZ + kB + tx * 4] = v;
    }
    if (jB != kB) {
        #pragma unroll
        for (int a = 0; a < 4; a++)
            #pragma unroll
            for (int c = 0; c < 4; c++)
                G[(size_t)(kB + tx * 4 + c) * N_SZ + jB + ty * 4 + a] = acc[a][c];
    }
}

// ---------------------------------------------------------------------------
// Kernel 3: 400-iteration PGD, matvecs via mma.sync (HMMA) from SMEM fp16
// triangles. 512 threads = 16 warps = (2 matrices x 8 output bands).
// Each warp: 32 output rows, full K=256: per virtual k-tile, ldmatrix(.trans
// for mirrored tiles) A-frags + B-frag built from w (col 0 only), fp32 acc.
// ---------------------------------------------------------------------------
__global__ __launch_bounds__(512, 1) void pgd_mma_kernel(const float* __restrict__ mu,
                                                         float* __restrict__ out) {
    extern __shared__ unsigned char sm[];
    const uint32_t smb = smem_u32(sm);
    const int b = blockIdx.x;
    const int t = threadIdx.x;
    const int lane = t & 31;
    const int wid = t >> 5;

    const float* __restrict__ G1g = g_G1 + (size_t)b * (N_SZ * N_SZ);
    const float* __restrict__ G2g = g_G2 + (size_t)b * (N_SZ * N_SZ);

    // ---- load fp16 triangles into padded tile layout ----
    #pragma unroll 1
    for (int m = 0; m < 2; m++) {
        const float* __restrict__ Gg = m ? G2g : G1g;
        unsigned char* dstm = sm + SM_TILES + m * MAT_BYTES;
        #pragma unroll 1
        for (int tix = 0; tix < NTILES; tix++) {
            const int a0 = c_TA[tix], b0 = c_TB[tix];
            const int i = t >> 4;        // row 0..31
            const int jp = t & 15;       // half2 pair 0..15
            const float2 f =
                *(const float2*)(Gg + (size_t)(a0 * 32 + i) * N_SZ + b0 * 32 + 2 * jp);
            const __half2 h = __floats2half2_rn(f.x, f.y);
            *(uint32_t*)(dstm + tix * TILE_BYTES + i * TILE_STRIDE_B + jp * 4) =
                *(const uint32_t*)&h;
        }
    }

    const int mtx = wid & 1;     // 0 -> G1, 1 -> G2
    const int r   = wid >> 1;    // output band
    const uint32_t tbase = smb + SM_TILES + (uint32_t)mtx * MAT_BYTES;
    float* const ybuf = (float*)(sm + (mtx ? SM_Y2 : SM_Y1));
    float* const y1s = (float*)(sm + SM_Y1);
    float* const y2s = (float*)(sm + SM_Y2);

    // lane-dependent ldmatrix offsets (bytes)
    const uint32_t lane_nt = (uint32_t)((lane & 7) + (lane & 8)) * TILE_STRIDE_B
                           + (uint32_t)((lane & 16) >> 1) * 2;
    const uint32_t lane_tr = (uint32_t)((lane & 7) + ((lane & 16) >> 1)) * TILE_STRIDE_B
                           + (uint32_t)(lane & 8) * 2;

    // ---- warp0 persistent solver state ----
    float wv[8], mu_r[8];
    float tau = 0.0f;
    const float step = g_step[b];
    if (wid == 0) {
        #pragma unroll
        for (int k = 0; k < 8; k++) {
            wv[k] = 1.0f / (float)N_SZ;
            mu_r[k] = mu[(size_t)b * N_SZ + lane + (k << 5)];
            const __half h = __float2half_rn(wv[k]);
            asm volatile("st.shared.u16 [%0], %1;"
                         :: "r"(smb + SM_W + (uint32_t)(lane + (k << 5)) * 2),
                            "h"(__half_as_ushort(h)) : "memory");
        }
    }
    __syncthreads();

    #pragma unroll 1
    for (int it = 0; it < N_ITERS; it++) {
        // ---- HMMA matvec: y[32r..32r+31] of matrix mtx ----
        float cA[4] = {0.f, 0.f, 0.f, 0.f};   // rows 32r+0..15
        float cB[4] = {0.f, 0.f, 0.f, 0.f};   // rows 32r+16..31
        #pragma unroll
        for (int bb = 0; bb < 8; bb++) {
            const bool tr = (bb < r);
            const int aa = tr ? bb : r;
            const int bn = tr ? r : bb;
            const uint32_t tile = tbase + (uint32_t)tri_idx(aa, bn) * TILE_BYTES;
            #pragma unroll
            for (int ks = 0; ks < 2; ks++) {
                // B fragment: w k-slice, col 0 only (lanes 0-3), zero elsewhere
                uint32_t b0, b1;
                const uint32_t waddr = smb + SM_W + (uint32_t)(bb * 64 + ks * 32)
                                     + (uint32_t)(lane & 3) * 4;
                asm volatile("ld.shared.b32 %0, [%1];" : "=r"(b0) : "r"(waddr));
                asm volatile("ld.shared.b32 %0, [%1];" : "=r"(b1) : "r"(waddr + 16));
                if (lane >= 4) { b0 = 0u; b1 = 0u; }

                uint32_t a0, a1, a2, a3;
                if (tr) {
                    // stored tile = (aa=k-band rows, bn=r cols); read transposed
                    const uint32_t base = tile + (uint32_t)ks * (16 * TILE_STRIDE_B)
                                        + lane_tr;
                    ldsm4t(a0, a1, a2, a3, base);           // ms = 0
                    mma16816(cA, a0, a1, a2, a3, b0, b1);
                    ldsm4t(a0, a1, a2, a3, base + 32);      // ms = 16 (cols +16)
                    mma16816(cB, a0, a1, a2, a3, b0, b1);
                } else {
                    const uint32_t base = tile + (uint32_t)ks * 32 + lane_nt;
                    ldsm4(a0, a1, a2, a3, base);            // ms = 0
                    mma16816(cA, a0, a1, a2, a3, b0, b1);
                    ldsm4(a0, a1, a2, a3, base + 16 * TILE_STRIDE_B); // ms = 16
                    mma16816(cB, a0, a1, a2, a3, b0, b1);
                }
            }
        }
        // D col 0 lives in threads lane%4==0: c0 -> row g, c2 -> row g+8
        if ((lane & 3) == 0) {
            const int g = lane >> 2;
            ybuf[32 * r + g]      = cA[0];
            ybuf[32 * r + 8 + g]  = cA[2];
            ybuf[32 * r + 16 + g] = cB[0];
            ybuf[32 * r + 24 + g] = cB[2];
        }
        __syncthreads();

        // ---- warp0: nrm, gradient step, warm-started Newton projection ----
        if (wid == 0) {
            float y1v[8], y2v[8];
            float prod = 0.f;
            #pragma unroll
            for (int k = 0; k < 8; k++) {
                const int c = lane + (k << 5);
                y1v[k] = y1s[c];
                y2v[k] = y2s[c];
                prod = fmaf(wv[k], y2v[k], prod);
            }
            #pragma unroll
            for (int o = 16; o; o >>= 1)
                prod += __shfl_xor_sync(0xFFFFFFFFu, prod, o);
            const float nrm = sqrtf(fmaxf(prod, 1e-12f));
            const float kin = KAPPA / nrm;

            float v[8];
            #pragma unroll
            for (int k = 0; k < 8; k++) {
                const float grad = -mu_r[k] + LAMBD * y1v[k] + kin * y2v[k];
                v[k] = wv[k] - step * grad;
            }

            // Newton on f(tau) = sum(relu(v-tau)) - 1 (convex, pw-linear).
            // Tangent root never exceeds the true root -> warm start is safe;
            // cnt==0 means tau beyond max(v): fall back to the lower bound.
            float tt = tau;
            bool fb = false;
            for (int ni = 0; ni < 24; ni++) {
                float s = 0.f;
                int cnt = 0;
                #pragma unroll
                for (int k = 0; k < 8; k++) {
                    const float d = v[k] - tt;
                    if (d > 0.f) { s += d; cnt++; }
                }
                #pragma unroll
                for (int o = 16; o; o >>= 1)
                    s += __shfl_xor_sync(0xFFFFFFFFu, s, o);
                cnt = __reduce_add_sync(0xFFFFFFFFu, cnt);
                if (cnt == 0) {
                    if (fb) break;
                    fb = true;
                    float S = 0.f;
                    #pragma unroll
                    for (int k = 0; k < 8; k++) S += v[k];
                    #pragma unroll
                    for (int o = 16; o; o >>= 1)
                        S += __shfl_xor_sync(0xFFFFFFFFu, S, o);
                    tt = (S - 1.0f) * (1.0f / (float)N_SZ);
                    continue;
                }
                const float delta = (s - 1.0f) / (float)cnt;
                tt += delta;
                if (fabsf(delta) <= 1e-10f) break;
            }
            tau = tt;

            #pragma unroll
            for (int k = 0; k < 8; k++) {
                wv[k] = fmaxf(v[k] - tau, 0.f);
                const __half h = __float2half_rn(wv[k]);
                asm volatile("st.shared.u16 [%0], %1;"
                             :: "r"(smb + SM_W + (uint32_t)(lane + (k << 5)) * 2),
                                "h"(__half_as_ushort(h)) : "memory");
            }
        }
        __syncthreads();
    }

    // ---- final clamp + renormalize, direct to gmem ----
    if (wid == 0) {
        float s = 0.f;
        #pragma unroll
        for (int k = 0; k < 8; k++) { wv[k] = fmaxf(wv[k], 0.f); s += wv[k]; }
        #pragma unroll
        for (int o = 16; o; o >>= 1) s += __shfl_xor_sync(0xFFFFFFFFu, s, o);
        const float inv = 1.0f / (s + 1e-12f);
        #pragma unroll
        for (int k = 0; k < 8; k++)
            out[(size_t)b * N_SZ + lane + (k << 5)] = wv[k] * inv;
    }
}

// ---------------------------------------------------------------------------
// Launcher
// ---------------------------------------------------------------------------
extern "C" void kernel_launch(void* const* d_in, const int* in_sizes, int n_in,
                              void* d_out, int out_size) {
    const float* mu = (const float*)d_in[0];
    const float* U  = (const float*)d_in[1];
    const float* A  = (const float*)d_in[2];
    float* out = (float*)d_out;

    cudaFuncSetAttribute(pgd_mma_kernel, cudaFuncAttributeMaxDynamicSharedMemorySize,
                         SM_TOTAL);

    step_kernel<<<B_SZ, 256>>>(U, A);

    dim3 gsyrk(10, 1, 2 * B_SZ);
    syrk_kernel<<<gsyrk, 256>>>(U, A);

    pgd_mma_kernel<<<B_SZ, 512, SM_TOTAL>>>(mu, out);
}

// round 6
// speedup vs baseline: 7.8648x; 1.0426x over previous
#include <cuda_runtime.h>
#include <cuda_fp16.h>
#include <math.h>
#include <stdint.h>

// Problem constants
#define B_SZ    512
#define N_SZ    256
#define N_ITERS 400
#define LAMBD   1.0f
#define KAPPA   0.1f

// Scratch: G1 = U^T U, G2 = A^T A (full, fp32) per batch; per-batch step.
__device__ float g_G1[(size_t)B_SZ * N_SZ * N_SZ];
__device__ float g_G2[(size_t)B_SZ * N_SZ * N_SZ];
__device__ float g_step[B_SZ];

// 32x32 tiles over the 8x8 tile-grid upper triangle: 36 tiles per matrix.
#define NTILES 36
__constant__ int c_TA[NTILES] = {0,0,0,0,0,0,0,0, 1,1,1,1,1,1,1, 2,2,2,2,2,2,
                                 3,3,3,3,3, 4,4,4,4, 5,5,5, 6,6, 7};
__constant__ int c_TB[NTILES] = {0,1,2,3,4,5,6,7, 1,2,3,4,5,6,7, 2,3,4,5,6,7,
                                 3,4,5,6,7, 4,5,6,7, 5,6,7, 6,7, 7};

__device__ __forceinline__ int tri_idx(int a, int b) {  // a <= b
    return a * 8 - (a * (a - 1)) / 2 + (b - a);
}

// Tile: 32 rows x 40 halves (80B stride; rows 0..7 land on distinct 16B
// segments mod 128 -> ldmatrix conflict-free, both orientations)
#define TILE_STRIDE_B 80
#define TILE_BYTES    (32 * TILE_STRIDE_B)      // 2560
#define MAT_BYTES     (NTILES * TILE_BYTES)     // 92160

// SMEM layout (PGD kernel)
#define SM_WPRIV 0                               // 8 warps x 512 B private w
#define SM_Y1    4096                            // [2][256] f32 (double buffer)
#define SM_Y2    6144                            // [2][256] f32
#define SM_PROD  8192                            // [2][8] f32
#define SM_TILES 10240
#define SM_TOTAL (SM_TILES + 2 * MAT_BYTES)      // 194560

// ---------------------------------------------------------------------------
// PTX helpers (base PTX only; no 'a'-gated instructions)
// ---------------------------------------------------------------------------
__device__ __forceinline__ uint32_t smem_u32(const void* p) {
    uint32_t a;
    asm("{ .reg .u64 t; cvta.to.shared.u64 t, %1; cvt.u32.u64 %0, t; }"
        : "=r"(a) : "l"(p));
    return a;
}

__device__ __forceinline__ void ldsm4(uint32_t& a0, uint32_t& a1, uint32_t& a2,
                                      uint32_t& a3, uint32_t addr) {
    asm volatile("ldmatrix.sync.aligned.m8n8.x4.shared.b16 {%0,%1,%2,%3}, [%4];"
                 : "=r"(a0), "=r"(a1), "=r"(a2), "=r"(a3) : "r"(addr));
}
__device__ __forceinline__ void ldsm4t(uint32_t& a0, uint32_t& a1, uint32_t& a2,
                                       uint32_t& a3, uint32_t addr) {
    asm volatile("ldmatrix.sync.aligned.m8n8.x4.trans.shared.b16 {%0,%1,%2,%3}, [%4];"
                 : "=r"(a0), "=r"(a1), "=r"(a2), "=r"(a3) : "r"(addr));
}
__device__ __forceinline__ void mma16816(float* c, uint32_t a0, uint32_t a1,
                                         uint32_t a2, uint32_t a3,
                                         uint32_t b0, uint32_t b1) {
    asm volatile(
        "mma.sync.aligned.m16n8k16.row.col.f32.f16.f16.f32 "
        "{%0,%1,%2,%3}, {%4,%5,%6,%7}, {%8,%9}, {%0,%1,%2,%3};"
        : "+f"(c[0]), "+f"(c[1]), "+f"(c[2]), "+f"(c[3])
        : "r"(a0), "r"(a1), "r"(a2), "r"(a3), "r"(b0), "r"(b1));
}

// ---------------------------------------------------------------------------
// Kernel 1: per-batch step size
// ---------------------------------------------------------------------------
__global__ __launch_bounds__(256) void step_kernel(const float* __restrict__ U,
                                                   const float* __restrict__ A) {
    const int b = blockIdx.x;
    const int t = threadIdx.x;
    const float* Ub = U + (size_t)b * (N_SZ * N_SZ);
    const float* Ab = A + (size_t)b * (N_SZ * N_SZ);

    float su = 0.f, sa = 0.f;
    #pragma unroll 4
    for (int idx = t; idx < N_SZ * N_SZ; idx += 256) {
        float u = Ub[idx]; su = fmaf(u, u, su);
        float a = Ab[idx]; sa = fmaf(a, a, sa);
    }
    __shared__ float rs_u[8], rs_a[8];
    #pragma unroll
    for (int o = 16; o; o >>= 1) {
        su += __shfl_xor_sync(0xFFFFFFFFu, su, o);
        sa += __shfl_xor_sync(0xFFFFFFFFu, sa, o);
    }
    if ((t & 31) == 0) { rs_u[t >> 5] = su; rs_a[t >> 5] = sa; }
    __syncthreads();
    if (t == 0) {
        float tu = 0.f, ta = 0.f;
        #pragma unroll
        for (int q = 0; q < 8; q++) { tu += rs_u[q]; ta += rs_a[q]; }
        g_step[b] = 1.0f / (LAMBD * tu + KAPPA * sqrtf(ta) + 1.0f);
    }
}

// ---------------------------------------------------------------------------
// Kernel 2: batched SYRK G = X^T X (upper-triangle tile-pairs + mirror)
// ---------------------------------------------------------------------------
__global__ __launch_bounds__(256) void syrk_kernel(const float* __restrict__ U,
                                                   const float* __restrict__ A) {
    const int mat = blockIdx.z;
    const int b = mat & (B_SZ - 1);
    const bool isA = (mat >= B_SZ);
    const float* X = (isA ? A : U) + (size_t)b * (N_SZ * N_SZ);
    float* G = (isA ? g_G2 : g_G1) + (size_t)b * (N_SZ * N_SZ);

    const int m = blockIdx.x;
    int tj, tk;
    if (m < 4)      { tj = 0; tk = m; }
    else if (m < 7) { tj = 1; tk = m - 3; }
    else if (m < 9) { tj = 2; tk = m - 5; }
    else            { tj = 3; tk = 3; }
    const int jB = tj * 64;
    const int kB = tk * 64;

    __shared__ float Xa[16][64];
    __shared__ float Xb[16][64];

    const int tid = threadIdx.x;
    const int tx = tid & 15;
    const int ty = tid >> 4;

    float acc[4][4];
    #pragma unroll
    for (int a = 0; a < 4; a++)
        #pragma unroll
        for (int c = 0; c < 4; c++) acc[a][c] = 0.f;

    for (int i0 = 0; i0 < N_SZ; i0 += 16) {
        #pragma unroll
        for (int e = 0; e < 4; e++) {
            int l = e * 256 + tid;
            int r = l >> 6, c = l & 63;
            Xa[r][c] = X[(size_t)(i0 + r) * N_SZ + jB + c];
            Xb[r][c] = X[(size_t)(i0 + r) * N_SZ + kB + c];
        }
        __syncthreads();
        #pragma unroll
        for (int kk = 0; kk < 16; kk++) {
            float4 av = *(const float4*)&Xa[kk][ty * 4];
            float4 bv = *(const float4*)&Xb[kk][tx * 4];
            float ar[4] = {av.x, av.y, av.z, av.w};
            float br[4] = {bv.x, bv.y, bv.z, bv.w};
            #pragma unroll
            for (int a = 0; a < 4; a++)
                #pragma unroll
                for (int c = 0; c < 4; c++)
                    acc[a][c] = fmaf(ar[a], br[c], acc[a][c]);
        }
        __syncthreads();
    }
    #pragma unroll
    for (int a = 0; a < 4; a++) {
        float4 v = make_float4(acc[a][0], acc[a][1], acc[a][2], acc[a][3]);
        *(float4*)&G[(size_t)(jB + ty * 4 + a) * N_SZ + kB + tx * 4] = v;
    }
    if (jB != kB) {
        #pragma unroll
        for (int a = 0; a < 4; a++)
            #pragma unroll
            for (int c = 0; c < 4; c++)
                G[(size_t)(kB + tx * 4 + c) * N_SZ + jB + ty * 4 + a] = acc[a][c];
    }
}

// ---------------------------------------------------------------------------
// Kernel 3: 400-iteration PGD. 256 threads = 8 warps; warp r computes output
// band r for BOTH matrices (b-fragments shared). Projection replicated in all
// warps (bitwise-identical), each warp owns a private w buffer -> ONE
// __syncthreads per iteration; y partials double-buffered by parity.
// ---------------------------------------------------------------------------
__global__ __launch_bounds__(256, 1) void pgd_mma_kernel(const float* __restrict__ mu,
                                                         float* __restrict__ out) {
    extern __shared__ unsigned char sm[];
    const uint32_t smb = smem_u32(sm);
    const int b = blockIdx.x;
    const int t = threadIdx.x;
    const int lane = t & 31;
    const int r = t >> 5;                   // warp id == output band

    const float* __restrict__ G1g = g_G1 + (size_t)b * (N_SZ * N_SZ);
    const float* __restrict__ G2g = g_G2 + (size_t)b * (N_SZ * N_SZ);

    // ---- load fp16 triangles into padded tile layout ----
    #pragma unroll 1
    for (int m = 0; m < 2; m++) {
        const float* __restrict__ Gg = m ? G2g : G1g;
        unsigned char* dstm = sm + SM_TILES + m * MAT_BYTES;
        #pragma unroll 1
        for (int tix = 0; tix < NTILES; tix++) {
            const int a0 = c_TA[tix], b0 = c_TB[tix];
            #pragma unroll
            for (int e = 0; e < 2; e++) {
                const int idx = t + 256 * e;      // 0..511
                const int i = idx >> 4;           // row 0..31
                const int jp = idx & 15;          // half2 pair 0..15
                const float2 f = *(const float2*)(Gg + (size_t)(a0 * 32 + i) * N_SZ
                                                  + b0 * 32 + 2 * jp);
                const __half2 h = __floats2half2_rn(f.x, f.y);
                *(uint32_t*)(dstm + tix * TILE_BYTES + i * TILE_STRIDE_B + jp * 4) =
                    *(const uint32_t*)&h;
            }
        }
    }

    const uint32_t t1base = smb + SM_TILES;
    const uint32_t t2base = smb + SM_TILES + MAT_BYTES;
    const uint32_t wpriv = smb + SM_WPRIV + (uint32_t)r * 512;

    // lane-dependent ldmatrix offsets (bytes)
    const uint32_t lane_nt = (uint32_t)((lane & 7) + (lane & 8)) * TILE_STRIDE_B
                           + (uint32_t)((lane & 16) >> 1) * 2;
    const uint32_t lane_tr = (uint32_t)((lane & 7) + ((lane & 16) >> 1)) * TILE_STRIDE_B
                           + (uint32_t)(lane & 8) * 2;

    // ---- replicated solver state (identical in every warp) ----
    float wv[8], mu_r[8];
    float tau = 0.0f;
    const float step = g_step[b];
    #pragma unroll
    for (int k = 0; k < 8; k++) {
        wv[k] = 1.0f / (float)N_SZ;
        mu_r[k] = mu[(size_t)b * N_SZ + lane + (k << 5)];
        const __half h = __float2half_rn(wv[k]);
        asm volatile("st.shared.u16 [%0], %1;"
                     :: "r"(wpriv + (uint32_t)(lane + (k << 5)) * 2),
                        "h"(__half_as_ushort(h)) : "memory");
    }
    __syncwarp();
    __syncthreads();

    #pragma unroll 1
    for (int it = 0; it < N_ITERS; it++) {
        const uint32_t buf = (uint32_t)(it & 1);
        float* const y1s = (float*)(sm + SM_Y1 + buf * 1024);
        float* const y2s = (float*)(sm + SM_Y2 + buf * 1024);
        float* const prods = (float*)(sm + SM_PROD + buf * 32);

        // ---- HMMA matvec: band r of G1 and G2 (shared b-fragments) ----
        float c1A[4] = {0.f,0.f,0.f,0.f}, c1B[4] = {0.f,0.f,0.f,0.f};
        float c2A[4] = {0.f,0.f,0.f,0.f}, c2B[4] = {0.f,0.f,0.f,0.f};
        #pragma unroll
        for (int bb = 0; bb < 8; bb++) {
            const bool tr = (bb < r);
            const int aa = tr ? bb : r;
            const int bn = tr ? r : bb;
            const uint32_t toff = (uint32_t)tri_idx(aa, bn) * TILE_BYTES;
            const uint32_t tile1 = t1base + toff;
            const uint32_t tile2 = t2base + toff;
            #pragma unroll
            for (int ks = 0; ks < 2; ks++) {
                uint32_t b0, b1;
                const uint32_t waddr = wpriv + (uint32_t)(bb * 64 + ks * 32)
                                     + (uint32_t)(lane & 3) * 4;
                asm volatile("ld.shared.b32 %0, [%1];" : "=r"(b0) : "r"(waddr));
                asm volatile("ld.shared.b32 %0, [%1];" : "=r"(b1) : "r"(waddr + 16));
                if (lane >= 4) { b0 = 0u; b1 = 0u; }

                uint32_t a0, a1, a2, a3;
                if (tr) {
                    const uint32_t o = (uint32_t)ks * (16 * TILE_STRIDE_B) + lane_tr;
                    ldsm4t(a0, a1, a2, a3, tile1 + o);
                    mma16816(c1A, a0, a1, a2, a3, b0, b1);
                    ldsm4t(a0, a1, a2, a3, tile1 + o + 32);
                    mma16816(c1B, a0, a1, a2, a3, b0, b1);
                    ldsm4t(a0, a1, a2, a3, tile2 + o);
                    mma16816(c2A, a0, a1, a2, a3, b0, b1);
                    ldsm4t(a0, a1, a2, a3, tile2 + o + 32);
                    mma16816(c2B, a0, a1, a2, a3, b0, b1);
                } else {
                    const uint32_t o = (uint32_t)ks * 32 + lane_nt;
                    ldsm4(a0, a1, a2, a3, tile1 + o);
                    mma16816(c1A, a0, a1, a2, a3, b0, b1);
                    ldsm4(a0, a1, a2, a3, tile1 + o + 16 * TILE_STRIDE_B);
                    mma16816(c1B, a0, a1, a2, a3, b0, b1);
                    ldsm4(a0, a1, a2, a3, tile2 + o);
                    mma16816(c2A, a0, a1, a2, a3, b0, b1);
                    ldsm4(a0, a1, a2, a3, tile2 + o + 16 * TILE_STRIDE_B);
                    mma16816(c2B, a0, a1, a2, a3, b0, b1);
                }
            }
        }

        // ---- store y bands (col 0 -> lanes lane%4==0) + fused prod partial ----
        const int g = lane >> 2;
        if ((lane & 3) == 0) {
            y1s[32 * r + g]      = c1A[0];
            y1s[32 * r + 8 + g]  = c1A[2];
            y1s[32 * r + 16 + g] = c1B[0];
            y1s[32 * r + 24 + g] = c1B[2];
            y2s[32 * r + g]      = c2A[0];
            y2s[32 * r + 8 + g]  = c2A[2];
            y2s[32 * r + 16 + g] = c2B[0];
            y2s[32 * r + 24 + g] = c2B[2];
        }
        // prod partial: p_r = sum over band rows of w_i * y2_i
        {
            const float wg0 = __shfl_sync(0xFFFFFFFFu, wv[r], g);
            const float wg1 = __shfl_sync(0xFFFFFFFFu, wv[r], g + 8);
            const float wg2 = __shfl_sync(0xFFFFFFFFu, wv[r], g + 16);
            const float wg3 = __shfl_sync(0xFFFFFFFFu, wv[r], g + 24);
            float p = c2A[0] * wg0 + c2A[2] * wg1 + c2B[0] * wg2 + c2B[2] * wg3;
            p += __shfl_xor_sync(0xFFFFFFFFu, p, 4);
            p += __shfl_xor_sync(0xFFFFFFFFu, p, 8);
            p += __shfl_xor_sync(0xFFFFFFFFu, p, 16);
            if (lane == 0) prods[r] = p;
        }
        __syncthreads();   // the ONLY barrier per iteration

        // ---- replicated projection (identical in every warp) ----
        float pr = 0.f;
        #pragma unroll
        for (int q = 0; q < 8; q++) pr += prods[q];
        const float nrm = sqrtf(fmaxf(pr, 1e-12f));
        const float kin = KAPPA / nrm;

        float v[8];
        #pragma unroll
        for (int k = 0; k < 8; k++) {
            const int c = lane + (k << 5);
            const float grad = -mu_r[k] + LAMBD * y1s[c] + kin * y2s[c];
            v[k] = wv[k] - step * grad;
        }

        // Newton on f(tau) = sum(relu(v-tau)) - 1 (convex, pw-linear).
        // Tangent root never exceeds the true root -> warm start safe;
        // cnt==0 (tau beyond max(v)) -> restart from the global lower bound.
        float tt = tau;
        bool fb = false;
        for (int ni = 0; ni < 24; ni++) {
            float s = 0.f;
            float cntf = 0.f;
            #pragma unroll
            for (int k = 0; k < 8; k++) {
                const float d = v[k] - tt;
                if (d > 0.f) { s += d; cntf += 1.0f; }
            }
            #pragma unroll
            for (int o = 16; o; o >>= 1) {
                s    += __shfl_xor_sync(0xFFFFFFFFu, s, o);
                cntf += __shfl_xor_sync(0xFFFFFFFFu, cntf, o);
            }
            if (cntf < 0.5f) {
                if (fb) break;
                fb = true;
                float S = 0.f;
                #pragma unroll
                for (int k = 0; k < 8; k++) S += v[k];
                #pragma unroll
                for (int o = 16; o; o >>= 1)
                    S += __shfl_xor_sync(0xFFFFFFFFu, S, o);
                tt = (S - 1.0f) * (1.0f / (float)N_SZ);
                continue;
            }
            const float delta = (s - 1.0f) / cntf;
            tt += delta;
            if (fabsf(delta) <= 1e-10f) break;
        }
        tau = tt;

        #pragma unroll
        for (int k = 0; k < 8; k++) {
            wv[k] = fmaxf(v[k] - tau, 0.f);
            const __half h = __float2half_rn(wv[k]);
            asm volatile("st.shared.u16 [%0], %1;"
                         :: "r"(wpriv + (uint32_t)(lane + (k << 5)) * 2),
                            "h"(__half_as_ushort(h)) : "memory");
        }
        __syncwarp();   // private w visible warp-wide before next matvec
    }

    // ---- final clamp + renormalize (warp 0 writes) ----
    if (r == 0) {
        float s = 0.f;
        #pragma unroll
        for (int k = 0; k < 8; k++) { wv[k] = fmaxf(wv[k], 0.f); s += wv[k]; }
        #pragma unroll
        for (int o = 16; o; o >>= 1) s += __shfl_xor_sync(0xFFFFFFFFu, s, o);
        const float inv = 1.0f / (s + 1e-12f);
        #pragma unroll
        for (int k = 0; k < 8; k++)
            out[(size_t)b * N_SZ + lane + (k << 5)] = wv[k] * inv;
    }
}

// ---------------------------------------------------------------------------
// Launcher
// ---------------------------------------------------------------------------
extern "C" void kernel_launch(void* const* d_in, const int* in_sizes, int n_in,
                              void* d_out, int out_size) {
    const float* mu = (const float*)d_in[0];
    const float* U  = (const float*)d_in[1];
    const float* A  = (const float*)d_in[2];
    float* out = (float*)d_out;

    cudaFuncSetAttribute(pgd_mma_kernel, cudaFuncAttributeMaxDynamicSharedMemorySize,
                         SM_TOTAL);

    step_kernel<<<B_SZ, 256>>>(U, A);

    dim3 gsyrk(10, 1, 2 * B_SZ);
    syrk_kernel<<<gsyrk, 256>>>(U, A);

    pgd_mma_kernel<<<B_SZ, 256, SM_TOTAL>>>(mu, out);
}

// round 7
// speedup vs baseline: 8.8094x; 1.1201x over previous
#include <cuda_runtime.h>
#include <cuda_fp16.h>
#include <math.h>
#include <stdint.h>

// Problem constants
#define B_SZ    512
#define N_SZ    256
#define N_ITERS 400
#define LAMBD   1.0f
#define KAPPA   0.1f

// Scratch: G1 = U^T U, G2 = A^T A (full, fp32) per batch; per-batch step.
__device__ float g_G1[(size_t)B_SZ * N_SZ * N_SZ];
__device__ float g_G2[(size_t)B_SZ * N_SZ * N_SZ];
__device__ float g_step[B_SZ];

// 32x32 tiles over the 8x8 tile-grid upper triangle: 36 tiles per matrix.
#define NTILES 36
__constant__ int c_TA[NTILES] = {0,0,0,0,0,0,0,0, 1,1,1,1,1,1,1, 2,2,2,2,2,2,
                                 3,3,3,3,3, 4,4,4,4, 5,5,5, 6,6, 7};
__constant__ int c_TB[NTILES] = {0,1,2,3,4,5,6,7, 1,2,3,4,5,6,7, 2,3,4,5,6,7,
                                 3,4,5,6,7, 4,5,6,7, 5,6,7, 6,7, 7};

__device__ __forceinline__ int tri_idx(int a, int b) {  // a <= b
    return a * 8 - (a * (a - 1)) / 2 + (b - a);
}

// Tile: 32 rows x 40 halves (80B stride; rows 0..7 land on distinct 16B
// segments mod 128 -> ldmatrix conflict-free, both orientations)
#define TILE_STRIDE_B 80
#define TILE_BYTES    (32 * TILE_STRIDE_B)      // 2560
#define MAT_BYTES     (NTILES * TILE_BYTES)     // 92160

// SMEM layout (PGD kernel)
#define SM_WPRIV 0                               // 8 warps x 512 B private w
#define SM_Y1    4096                            // [2][256] f32 (double buffer)
#define SM_Y2    6144                            // [2][256] f32
#define SM_PROD  8192                            // [2][8] f32
#define SM_TILES 10240
#define SM_TOTAL (SM_TILES + 2 * MAT_BYTES)      // 194560

// ---------------------------------------------------------------------------
// PTX helpers (base PTX only; no 'a'-gated instructions)
// ---------------------------------------------------------------------------
__device__ __forceinline__ uint32_t smem_u32(const void* p) {
    uint32_t a;
    asm("{ .reg .u64 t; cvta.to.shared.u64 t, %1; cvt.u32.u64 %0, t; }"
        : "=r"(a) : "l"(p));
    return a;
}

__device__ __forceinline__ void ldsm4(uint32_t& a0, uint32_t& a1, uint32_t& a2,
                                      uint32_t& a3, uint32_t addr) {
    asm volatile("ldmatrix.sync.aligned.m8n8.x4.shared.b16 {%0,%1,%2,%3}, [%4];"
                 : "=r"(a0), "=r"(a1), "=r"(a2), "=r"(a3) : "r"(addr));
}
__device__ __forceinline__ void ldsm4t(uint32_t& a0, uint32_t& a1, uint32_t& a2,
                                       uint32_t& a3, uint32_t addr) {
    asm volatile("ldmatrix.sync.aligned.m8n8.x4.trans.shared.b16 {%0,%1,%2,%3}, [%4];"
                 : "=r"(a0), "=r"(a1), "=r"(a2), "=r"(a3) : "r"(addr));
}
__device__ __forceinline__ void mma16816(float* c, uint32_t a0, uint32_t a1,
                                         uint32_t a2, uint32_t a3,
                                         uint32_t b0, uint32_t b1) {
    asm volatile(
        "mma.sync.aligned.m16n8k16.row.col.f32.f16.f16.f32 "
        "{%0,%1,%2,%3}, {%4,%5,%6,%7}, {%8,%9}, {%0,%1,%2,%3};"
        : "+f"(c[0]), "+f"(c[1]), "+f"(c[2]), "+f"(c[3])
        : "r"(a0), "r"(a1), "r"(a2), "r"(a3), "r"(b0), "r"(b1));
}

// ---------------------------------------------------------------------------
// Kernel 1: per-batch step size
// ---------------------------------------------------------------------------
__global__ __launch_bounds__(256) void step_kernel(const float* __restrict__ U,
                                                   const float* __restrict__ A) {
    const int b = blockIdx.x;
    const int t = threadIdx.x;
    const float* Ub = U + (size_t)b * (N_SZ * N_SZ);
    const float* Ab = A + (size_t)b * (N_SZ * N_SZ);

    float su = 0.f, sa = 0.f;
    #pragma unroll 4
    for (int idx = t; idx < N_SZ * N_SZ; idx += 256) {
        float u = Ub[idx]; su = fmaf(u, u, su);
        float a = Ab[idx]; sa = fmaf(a, a, sa);
    }
    __shared__ float rs_u[8], rs_a[8];
    #pragma unroll
    for (int o = 16; o; o >>= 1) {
        su += __shfl_xor_sync(0xFFFFFFFFu, su, o);
        sa += __shfl_xor_sync(0xFFFFFFFFu, sa, o);
    }
    if ((t & 31) == 0) { rs_u[t >> 5] = su; rs_a[t >> 5] = sa; }
    __syncthreads();
    if (t == 0) {
        float tu = 0.f, ta = 0.f;
        #pragma unroll
        for (int q = 0; q < 8; q++) { tu += rs_u[q]; ta += rs_a[q]; }
        g_step[b] = 1.0f / (LAMBD * tu + KAPPA * sqrtf(ta) + 1.0f);
    }
}

// ---------------------------------------------------------------------------
// Kernel 2: batched SYRK G = X^T X (upper-triangle tile-pairs + mirror)
// ---------------------------------------------------------------------------
__global__ __launch_bounds__(256) void syrk_kernel(const float* __restrict__ U,
                                                   const float* __restrict__ A) {
    const int mat = blockIdx.z;
    const int b = mat & (B_SZ - 1);
    const bool isA = (mat >= B_SZ);
    const float* X = (isA ? A : U) + (size_t)b * (N_SZ * N_SZ);
    float* G = (isA ? g_G2 : g_G1) + (size_t)b * (N_SZ * N_SZ);

    const int m = blockIdx.x;
    int tj, tk;
    if (m < 4)      { tj = 0; tk = m; }
    else if (m < 7) { tj = 1; tk = m - 3; }
    else if (m < 9) { tj = 2; tk = m - 5; }
    else            { tj = 3; tk = 3; }
    const int jB = tj * 64;
    const int kB = tk * 64;

    __shared__ float Xa[16][64];
    __shared__ float Xb[16][64];

    const int tid = threadIdx.x;
    const int tx = tid & 15;
    const int ty = tid >> 4;

    float acc[4][4];
    #pragma unroll
    for (int a = 0; a < 4; a++)
        #pragma unroll
        for (int c = 0; c < 4; c++) acc[a][c] = 0.f;

    for (int i0 = 0; i0 < N_SZ; i0 += 16) {
        #pragma unroll
        for (int e = 0; e < 4; e++) {
            int l = e * 256 + tid;
            int r = l >> 6, c = l & 63;
            Xa[r][c] = X[(size_t)(i0 + r) * N_SZ + jB + c];
            Xb[r][c] = X[(size_t)(i0 + r) * N_SZ + kB + c];
        }
        __syncthreads();
        #pragma unroll
        for (int kk = 0; kk < 16; kk++) {
            float4 av = *(const float4*)&Xa[kk][ty * 4];
            float4 bv = *(const float4*)&Xb[kk][tx * 4];
            float ar[4] = {av.x, av.y, av.z, av.w};
            float br[4] = {bv.x, bv.y, bv.z, bv.w};
            #pragma unroll
            for (int a = 0; a < 4; a++)
                #pragma unroll
                for (int c = 0; c < 4; c++)
                    acc[a][c] = fmaf(ar[a], br[c], acc[a][c]);
        }
        __syncthreads();
    }
    #pragma unroll
    for (int a = 0; a < 4; a++) {
        float4 v = make_float4(acc[a][0], acc[a][1], acc[a][2], acc[a][3]);
        *(float4*)&G[(size_t)(jB + ty * 4 + a) * N_SZ + kB + tx * 4] = v;
    }
    if (jB != kB) {
        #pragma unroll
        for (int a = 0; a < 4; a++)
            #pragma unroll
            for (int c = 0; c < 4; c++)
                G[(size_t)(kB + tx * 4 + c) * N_SZ + jB + ty * 4 + a] = acc[a][c];
    }
}

// ---------------------------------------------------------------------------
// Kernel 3: 400-iteration PGD. 256 threads = 8 warps; warp r = output band r
// for BOTH matrices. A-fragments for k-bands 0..3 are loaded ONCE into
// registers (128 regs/thread) and reused for all 400 iterations; k-bands 4..7
// stream from SMEM via ldmatrix. Projection replicated in all warps; private
// w buffers; ONE __syncthreads per iteration.
// ---------------------------------------------------------------------------
__global__ __launch_bounds__(256, 1) void pgd_mma_kernel(const float* __restrict__ mu,
                                                         float* __restrict__ out) {
    extern __shared__ unsigned char sm[];
    const uint32_t smb = smem_u32(sm);
    const int b = blockIdx.x;
    const int t = threadIdx.x;
    const int lane = t & 31;
    const int r = t >> 5;                   // warp id == output band

    const float* __restrict__ G1g = g_G1 + (size_t)b * (N_SZ * N_SZ);
    const float* __restrict__ G2g = g_G2 + (size_t)b * (N_SZ * N_SZ);

    // ---- load fp16 triangles into padded tile layout ----
    #pragma unroll 1
    for (int m = 0; m < 2; m++) {
        const float* __restrict__ Gg = m ? G2g : G1g;
        unsigned char* dstm = sm + SM_TILES + m * MAT_BYTES;
        #pragma unroll 1
        for (int tix = 0; tix < NTILES; tix++) {
            const int a0 = c_TA[tix], b0 = c_TB[tix];
            #pragma unroll
            for (int e = 0; e < 2; e++) {
                const int idx = t + 256 * e;      // 0..511
                const int i = idx >> 4;           // row 0..31
                const int jp = idx & 15;          // half2 pair 0..15
                const float2 f = *(const float2*)(Gg + (size_t)(a0 * 32 + i) * N_SZ
                                                  + b0 * 32 + 2 * jp);
                const __half2 h = __floats2half2_rn(f.x, f.y);
                *(uint32_t*)(dstm + tix * TILE_BYTES + i * TILE_STRIDE_B + jp * 4) =
                    *(const uint32_t*)&h;
            }
        }
    }

    const uint32_t t1base = smb + SM_TILES;
    const uint32_t t2base = smb + SM_TILES + MAT_BYTES;
    const uint32_t wpriv = smb + SM_WPRIV + (uint32_t)r * 512;

    // lane-dependent ldmatrix offsets (bytes)
    const uint32_t lane_nt = (uint32_t)((lane & 7) + (lane & 8)) * TILE_STRIDE_B
                           + (uint32_t)((lane & 16) >> 1) * 2;
    const uint32_t lane_tr = (uint32_t)((lane & 7) + ((lane & 16) >> 1)) * TILE_STRIDE_B
                           + (uint32_t)(lane & 8) * 2;

    __syncthreads();

    // ---- preload k-bands 0..3 A-fragments into registers (persist 400 iters)
    // fr[mat][bb][ks][mhalf][4 regs] -> 128 registers/thread
    uint32_t fr[2][4][2][2][4];
    #pragma unroll
    for (int m = 0; m < 2; m++) {
        const uint32_t tb = m ? t2base : t1base;
        #pragma unroll
        for (int bb = 0; bb < 4; bb++) {
            const bool tr = (bb < r);
            const int aa = tr ? bb : r;
            const int bn = tr ? r : bb;
            const uint32_t tile = tb + (uint32_t)tri_idx(aa, bn) * TILE_BYTES;
            #pragma unroll
            for (int ks = 0; ks < 2; ks++) {
                if (tr) {
                    const uint32_t o = (uint32_t)ks * (16 * TILE_STRIDE_B) + lane_tr;
                    ldsm4t(fr[m][bb][ks][0][0], fr[m][bb][ks][0][1],
                           fr[m][bb][ks][0][2], fr[m][bb][ks][0][3], tile + o);
                    ldsm4t(fr[m][bb][ks][1][0], fr[m][bb][ks][1][1],
                           fr[m][bb][ks][1][2], fr[m][bb][ks][1][3], tile + o + 32);
                } else {
                    const uint32_t o = (uint32_t)ks * 32 + lane_nt;
                    ldsm4(fr[m][bb][ks][0][0], fr[m][bb][ks][0][1],
                          fr[m][bb][ks][0][2], fr[m][bb][ks][0][3], tile + o);
                    ldsm4(fr[m][bb][ks][1][0], fr[m][bb][ks][1][1],
                          fr[m][bb][ks][1][2], fr[m][bb][ks][1][3],
                          tile + o + 16 * TILE_STRIDE_B);
                }
            }
        }
    }

    // ---- replicated solver state (identical in every warp) ----
    float wv[8], mu_r[8];
    float tau = 0.0f;
    const float step = g_step[b];
    #pragma unroll
    for (int k = 0; k < 8; k++) {
        wv[k] = 1.0f / (float)N_SZ;
        mu_r[k] = mu[(size_t)b * N_SZ + lane + (k << 5)];
        const __half h = __float2half_rn(wv[k]);
        asm volatile("st.shared.u16 [%0], %1;"
                     :: "r"(wpriv + (uint32_t)(lane + (k << 5)) * 2),
                        "h"(__half_as_ushort(h)) : "memory");
    }
    __syncwarp();
    __syncthreads();

    #pragma unroll 1
    for (int it = 0; it < N_ITERS; it++) {
        const uint32_t buf = (uint32_t)(it & 1);
        float* const y1s = (float*)(sm + SM_Y1 + buf * 1024);
        float* const y2s = (float*)(sm + SM_Y2 + buf * 1024);
        float* const prods = (float*)(sm + SM_PROD + buf * 32);

        float c1A[4] = {0.f,0.f,0.f,0.f}, c1B[4] = {0.f,0.f,0.f,0.f};
        float c2A[4] = {0.f,0.f,0.f,0.f}, c2B[4] = {0.f,0.f,0.f,0.f};

        // ---- k-bands 0..3: register-resident fragments ----
        #pragma unroll
        for (int bb = 0; bb < 4; bb++) {
            #pragma unroll
            for (int ks = 0; ks < 2; ks++) {
                uint32_t b0, b1;
                const uint32_t waddr = wpriv + (uint32_t)(bb * 64 + ks * 32)
                                     + (uint32_t)(lane & 3) * 4;
                asm volatile("ld.shared.b32 %0, [%1];" : "=r"(b0) : "r"(waddr));
                asm volatile("ld.shared.b32 %0, [%1];" : "=r"(b1) : "r"(waddr + 16));
                if (lane >= 4) { b0 = 0u; b1 = 0u; }

                mma16816(c1A, fr[0][bb][ks][0][0], fr[0][bb][ks][0][1],
                              fr[0][bb][ks][0][2], fr[0][bb][ks][0][3], b0, b1);
                mma16816(c1B, fr[0][bb][ks][1][0], fr[0][bb][ks][1][1],
                              fr[0][bb][ks][1][2], fr[0][bb][ks][1][3], b0, b1);
                mma16816(c2A, fr[1][bb][ks][0][0], fr[1][bb][ks][0][1],
                              fr[1][bb][ks][0][2], fr[1][bb][ks][0][3], b0, b1);
                mma16816(c2B, fr[1][bb][ks][1][0], fr[1][bb][ks][1][1],
                              fr[1][bb][ks][1][2], fr[1][bb][ks][1][3], b0, b1);
            }
        }

        // ---- k-bands 4..7: streamed from SMEM via ldmatrix ----
        #pragma unroll
        for (int bb = 4; bb < 8; bb++) {
            const bool tr = (bb < r);
            const int aa = tr ? bb : r;
            const int bn = tr ? r : bb;
            const uint32_t toff = (uint32_t)tri_idx(aa, bn) * TILE_BYTES;
            const uint32_t tile1 = t1base + toff;
            const uint32_t tile2 = t2base + toff;
            #pragma unroll
            for (int ks = 0; ks < 2; ks++) {
                uint32_t b0, b1;
                const uint32_t waddr = wpriv + (uint32_t)(bb * 64 + ks * 32)
                                     + (uint32_t)(lane & 3) * 4;
                asm volatile("ld.shared.b32 %0, [%1];" : "=r"(b0) : "r"(waddr));
                asm volatile("ld.shared.b32 %0, [%1];" : "=r"(b1) : "r"(waddr + 16));
                if (lane >= 4) { b0 = 0u; b1 = 0u; }

                uint32_t a0, a1, a2, a3;
                if (tr) {
                    const uint32_t o = (uint32_t)ks * (16 * TILE_STRIDE_B) + lane_tr;
                    ldsm4t(a0, a1, a2, a3, tile1 + o);
                    mma16816(c1A, a0, a1, a2, a3, b0, b1);
                    ldsm4t(a0, a1, a2, a3, tile1 + o + 32);
                    mma16816(c1B, a0, a1, a2, a3, b0, b1);
                    ldsm4t(a0, a1, a2, a3, tile2 + o);
                    mma16816(c2A, a0, a1, a2, a3, b0, b1);
                    ldsm4t(a0, a1, a2, a3, tile2 + o + 32);
                    mma16816(c2B, a0, a1, a2, a3, b0, b1);
                } else {
                    const uint32_t o = (uint32_t)ks * 32 + lane_nt;
                    ldsm4(a0, a1, a2, a3, tile1 + o);
                    mma16816(c1A, a0, a1, a2, a3, b0, b1);
                    ldsm4(a0, a1, a2, a3, tile1 + o + 16 * TILE_STRIDE_B);
                    mma16816(c1B, a0, a1, a2, a3, b0, b1);
                    ldsm4(a0, a1, a2, a3, tile2 + o);
                    mma16816(c2A, a0, a1, a2, a3, b0, b1);
                    ldsm4(a0, a1, a2, a3, tile2 + o + 16 * TILE_STRIDE_B);
                    mma16816(c2B, a0, a1, a2, a3, b0, b1);
                }
            }
        }

        // ---- store y bands (col 0 -> lanes lane%4==0) + fused prod partial ----
        const int g = lane >> 2;
        if ((lane & 3) == 0) {
            y1s[32 * r + g]      = c1A[0];
            y1s[32 * r + 8 + g]  = c1A[2];
            y1s[32 * r + 16 + g] = c1B[0];
            y1s[32 * r + 24 + g] = c1B[2];
            y2s[32 * r + g]      = c2A[0];
            y2s[32 * r + 8 + g]  = c2A[2];
            y2s[32 * r + 16 + g] = c2B[0];
            y2s[32 * r + 24 + g] = c2B[2];
        }
        {
            const float wg0 = __shfl_sync(0xFFFFFFFFu, wv[r], g);
            const float wg1 = __shfl_sync(0xFFFFFFFFu, wv[r], g + 8);
            const float wg2 = __shfl_sync(0xFFFFFFFFu, wv[r], g + 16);
            const float wg3 = __shfl_sync(0xFFFFFFFFu, wv[r], g + 24);
            float p = c2A[0] * wg0 + c2A[2] * wg1 + c2B[0] * wg2 + c2B[2] * wg3;
            p += __shfl_xor_sync(0xFFFFFFFFu, p, 4);
            p += __shfl_xor_sync(0xFFFFFFFFu, p, 8);
            p += __shfl_xor_sync(0xFFFFFFFFu, p, 16);
            if (lane == 0) prods[r] = p;
        }
        __syncthreads();   // the ONLY barrier per iteration

        // ---- replicated projection (identical in every warp) ----
        float pr = 0.f;
        #pragma unroll
        for (int q = 0; q < 8; q++) pr += prods[q];
        const float nrm = sqrtf(fmaxf(pr, 1e-12f));
        const float kin = KAPPA / nrm;

        float v[8];
        #pragma unroll
        for (int k = 0; k < 8; k++) {
            const int c = lane + (k << 5);
            const float grad = -mu_r[k] + LAMBD * y1s[c] + kin * y2s[c];
            v[k] = wv[k] - step * grad;
        }

        // Newton on f(tau) = sum(relu(v-tau)) - 1 (convex, pw-linear).
        float tt = tau;
        bool fb = false;
        for (int ni = 0; ni < 24; ni++) {
            float s = 0.f;
            float cntf = 0.f;
            #pragma unroll
            for (int k = 0; k < 8; k++) {
                const float d = v[k] - tt;
                if (d > 0.f) { s += d; cntf += 1.0f; }
            }
            #pragma unroll
            for (int o = 16; o; o >>= 1) {
                s    += __shfl_xor_sync(0xFFFFFFFFu, s, o);
                cntf += __shfl_xor_sync(0xFFFFFFFFu, cntf, o);
            }
            if (cntf < 0.5f) {
                if (fb) break;
                fb = true;
                float S = 0.f;
                #pragma unroll
                for (int k = 0; k < 8; k++) S += v[k];
                #pragma unroll
                for (int o = 16; o; o >>= 1)
                    S += __shfl_xor_sync(0xFFFFFFFFu, S, o);
                tt = (S - 1.0f) * (1.0f / (float)N_SZ);
                continue;
            }
            const float delta = (s - 1.0f) / cntf;
            tt += delta;
            if (fabsf(delta) <= 1e-10f) break;
        }
        tau = tt;

        #pragma unroll
        for (int k = 0; k < 8; k++) {
            wv[k] = fmaxf(v[k] - tau, 0.f);
            const __half h = __float2half_rn(wv[k]);
            asm volatile("st.shared.u16 [%0], %1;"
                         :: "r"(wpriv + (uint32_t)(lane + (k << 5)) * 2),
                            "h"(__half_as_ushort(h)) : "memory");
        }
        __syncwarp();   // private w visible warp-wide before next matvec
    }

    // ---- final clamp + renormalize (warp 0 writes) ----
    if (r == 0) {
        float s = 0.f;
        #pragma unroll
        for (int k = 0; k < 8; k++) { wv[k] = fmaxf(wv[k], 0.f); s += wv[k]; }
        #pragma unroll
        for (int o = 16; o; o >>= 1) s += __shfl_xor_sync(0xFFFFFFFFu, s, o);
        const float inv = 1.0f / (s + 1e-12f);
        #pragma unroll
        for (int k = 0; k < 8; k++)
            out[(size_t)b * N_SZ + lane + (k << 5)] = wv[k] * inv;
    }
}

// ---------------------------------------------------------------------------
// Launcher
// ---------------------------------------------------------------------------
extern "C" void kernel_launch(void* const* d_in, const int* in_sizes, int n_in,
                              void* d_out, int out_size) {
    const float* mu = (const float*)d_in[0];
    const float* U  = (const float*)d_in[1];
    const float* A  = (const float*)d_in[2];
    float* out = (float*)d_out;

    cudaFuncSetAttribute(pgd_mma_kernel, cudaFuncAttributeMaxDynamicSharedMemorySize,
                         SM_TOTAL);

    step_kernel<<<B_SZ, 256>>>(U, A);

    dim3 gsyrk(10, 1, 2 * B_SZ);
    syrk_kernel<<<gsyrk, 256>>>(U, A);

    pgd_mma_kernel<<<B_SZ, 256, SM_TOTAL>>>(mu, out);
}

// round 8
// speedup vs baseline: 10.4759x; 1.1892x over previous
#include <cuda_runtime.h>
#include <cuda_fp16.h>
#include <math.h>
#include <stdint.h>

// Problem constants
#define B_SZ    512
#define N_SZ    256
#define N_ITERS 400
#define LAMBD   1.0f
#define KAPPA   0.1f

// 32x32 tiles over the 8x8 tile-grid upper triangle: 36 tiles per matrix.
#define NTILES 36
__constant__ int c_TA[NTILES] = {0,0,0,0,0,0,0,0, 1,1,1,1,1,1,1, 2,2,2,2,2,2,
                                 3,3,3,3,3, 4,4,4,4, 5,5,5, 6,6, 7};
__constant__ int c_TB[NTILES] = {0,1,2,3,4,5,6,7, 1,2,3,4,5,6,7, 2,3,4,5,6,7,
                                 3,4,5,6,7, 4,5,6,7, 5,6,7, 6,7, 7};

__device__ __forceinline__ int tri_idx(int a, int b) {  // a <= b
    return a * 8 - (a * (a - 1)) / 2 + (b - a);
}

// fp16 G tile store: 32 rows x 40 halves (80B stride; rows 0..7 hit distinct
// 16B segments mod 128 -> ldmatrix conflict-free in both orientations)
#define TILE_STRIDE_B 80
#define TILE_BYTES    (32 * TILE_STRIDE_B)      // 2560
#define MAT_BYTES     (NTILES * TILE_BYTES)     // 92160
#define BATCH_BYTES   (2 * MAT_BYTES)           // 184320

// Global scratch: G triangles in fp16 tile layout + Frobenius sums.
__device__ unsigned char g_G16[(size_t)B_SZ * BATCH_BYTES];  // ~94 MB
__device__ float g_fro[2 * B_SZ];   // [0..511]=||U||_F^2, [512..1023]=||A||_F^2

// ---------------------------------------------------------------------------
// PTX helpers (base PTX only; no 'a'-gated instructions)
// ---------------------------------------------------------------------------
__device__ __forceinline__ uint32_t smem_u32(const void* p) {
    uint32_t a;
    asm("{ .reg .u64 t; cvta.to.shared.u64 t, %1; cvt.u32.u64 %0, t; }"
        : "=r"(a) : "l"(p));
    return a;
}
__device__ __forceinline__ void ldsm4(uint32_t& a0, uint32_t& a1, uint32_t& a2,
                                      uint32_t& a3, uint32_t addr) {
    asm volatile("ldmatrix.sync.aligned.m8n8.x4.shared.b16 {%0,%1,%2,%3}, [%4];"
                 : "=r"(a0), "=r"(a1), "=r"(a2), "=r"(a3) : "r"(addr));
}
__device__ __forceinline__ void ldsm4t(uint32_t& a0, uint32_t& a1, uint32_t& a2,
                                       uint32_t& a3, uint32_t addr) {
    asm volatile("ldmatrix.sync.aligned.m8n8.x4.trans.shared.b16 {%0,%1,%2,%3}, [%4];"
                 : "=r"(a0), "=r"(a1), "=r"(a2), "=r"(a3) : "r"(addr));
}
__device__ __forceinline__ void ldsm2t(uint32_t& r0, uint32_t& r1, uint32_t addr) {
    asm volatile("ldmatrix.sync.aligned.m8n8.x2.trans.shared.b16 {%0,%1}, [%2];"
                 : "=r"(r0), "=r"(r1) : "r"(addr));
}
__device__ __forceinline__ void mma16816(float* c, uint32_t a0, uint32_t a1,
                                         uint32_t a2, uint32_t a3,
                                         uint32_t b0, uint32_t b1) {
    asm volatile(
        "mma.sync.aligned.m16n8k16.row.col.f32.f16.f16.f32 "
        "{%0,%1,%2,%3}, {%4,%5,%6,%7}, {%8,%9}, {%0,%1,%2,%3};"
        : "+f"(c[0]), "+f"(c[1]), "+f"(c[2]), "+f"(c[3])
        : "r"(a0), "r"(a1), "r"(a2), "r"(a3), "r"(b0), "r"(b1));
}

// ---------------------------------------------------------------------------
// Kernel 1: batched SYRK via HMMA with split-fp16 inputs (error-compensated:
// x ~= xh + xl; G = XhT Xh + XhT Xl + XlT Xh, fp32 accum -> fp32-grade G).
// One CTA per (matrix, batch). Writes G triangle directly as fp16 tiles in
// pgd's layout, plus the Frobenius sum (replaces step_kernel).
// ---------------------------------------------------------------------------
#define XS_STRIDE 528                       // 256 halves + 8 pad, 16B aligned
#define XS_LBASE  (128 * XS_STRIDE)         // 67584
#define XS_SCR    (2 * 128 * XS_STRIDE)     // 135168
#define SYRK_SMEM (XS_SCR + 64)

__global__ __launch_bounds__(256, 1) void syrk16_kernel(const float* __restrict__ U,
                                                        const float* __restrict__ A) {
    extern __shared__ unsigned char sm[];
    const uint32_t smb = smem_u32(sm);
    const int mat = blockIdx.x >> 9;        // 0 -> U, 1 -> A
    const int b = blockIdx.x & (B_SZ - 1);
    const float* __restrict__ X = (mat ? A : U) + (size_t)b * (N_SZ * N_SZ);
    const int t = threadIdx.x;
    const int lane = t & 31;
    const int w = t >> 5;

    const uint32_t lane_tr = (uint32_t)((lane & 7) + ((lane & 16) >> 1)) * XS_STRIDE
                           + (uint32_t)(lane & 8) * 2;
    const uint32_t laneB = (uint32_t)(lane & 15) * XS_STRIDE;

    float fro = 0.f;
    float acc[5][2][4][4];
    #pragma unroll
    for (int q = 0; q < 5; q++)
        #pragma unroll
        for (int mh = 0; mh < 2; mh++)
            #pragma unroll
            for (int nq = 0; nq < 4; nq++)
                #pragma unroll
                for (int e = 0; e < 4; e++) acc[q][mh][nq][e] = 0.f;

    #pragma unroll 1
    for (int ch = 0; ch < 2; ch++) {
        if (ch) __syncthreads();   // all warps done reading chunk 0 tiles
        // ---- stage rows i in [128ch, 128ch+128) as split-fp16 ----
        #pragma unroll 4
        for (int idx = t; idx < 128 * 128; idx += 256) {
            const int ir = idx >> 7;
            const int jp = idx & 127;
            const float2 f = *(const float2*)(X + (size_t)(128 * ch + ir) * N_SZ + 2 * jp);
            fro = fmaf(f.x, f.x, fro);
            fro = fmaf(f.y, f.y, fro);
            const __half hx = __float2half_rn(f.x);
            const __half hy = __float2half_rn(f.y);
            const __half lx = __float2half_rn(f.x - __half2float(hx));
            const __half ly = __float2half_rn(f.y - __half2float(hy));
            *(__half2*)(sm + ir * XS_STRIDE + jp * 4) = __halves2half2(hx, hy);
            *(__half2*)(sm + XS_LBASE + ir * XS_STRIDE + jp * 4) = __halves2half2(lx, ly);
        }
        __syncthreads();

        // ---- compute this chunk's contribution for this warp's tiles ----
        #pragma unroll
        for (int q = 0; q < 5; q++) {
            const int tix = w + 8 * q;
            if (tix < NTILES) {
                const int a0 = c_TA[tix], b0 = c_TB[tix];
                const uint32_t acol = smb + (uint32_t)(a0 * 32) * 2 + lane_tr;
                const uint32_t bcol = smb + (uint32_t)(b0 * 32) * 2 + laneB;
                #pragma unroll
                for (int kc = 0; kc < 8; kc++) {
                    const uint32_t ro = (uint32_t)(kc * 16) * XS_STRIDE;
                    uint32_t AH[2][4], AL[2][4];
                    #pragma unroll
                    for (int mh = 0; mh < 2; mh++) {
                        const uint32_t ao = acol + ro + (uint32_t)(mh * 16) * 2;
                        ldsm4t(AH[mh][0], AH[mh][1], AH[mh][2], AH[mh][3], ao);
                        ldsm4t(AL[mh][0], AL[mh][1], AL[mh][2], AL[mh][3],
                               ao + XS_LBASE);
                    }
                    #pragma unroll
                    for (int nq = 0; nq < 4; nq++) {
                        const uint32_t bo = bcol + ro + (uint32_t)(nq * 8) * 2;
                        uint32_t bh0, bh1, bl0, bl1;
                        ldsm2t(bh0, bh1, bo);
                        ldsm2t(bl0, bl1, bo + XS_LBASE);
                        #pragma unroll
                        for (int mh = 0; mh < 2; mh++) {
                            float* c = acc[q][mh][nq];
                            mma16816(c, AH[mh][0], AH[mh][1], AH[mh][2], AH[mh][3],
                                     bh0, bh1);
                            mma16816(c, AH[mh][0], AH[mh][1], AH[mh][2], AH[mh][3],
                                     bl0, bl1);
                            mma16816(c, AL[mh][0], AL[mh][1], AL[mh][2], AL[mh][3],
                                     bh0, bh1);
                        }
                    }
                }
            }
        }
    }

    // ---- epilogue: write fp16 G tiles in pgd's layout ----
    unsigned char* gb = g_G16 + (size_t)b * BATCH_BYTES + (size_t)mat * MAT_BYTES;
    #pragma unroll
    for (int q = 0; q < 5; q++) {
        const int tix = w + 8 * q;
        if (tix < NTILES) {
            #pragma unroll
            for (int mh = 0; mh < 2; mh++)
                #pragma unroll
                for (int nq = 0; nq < 4; nq++) {
                    const float* c = acc[q][mh][nq];
                    const uint32_t o = (uint32_t)tix * TILE_BYTES
                        + (uint32_t)(mh * 16 + (lane >> 2)) * TILE_STRIDE_B
                        + (uint32_t)(nq * 4 + (lane & 3)) * 4;
                    *(__half2*)(gb + o) =
                        __halves2half2(__float2half_rn(c[0]), __float2half_rn(c[1]));
                    *(__half2*)(gb + o + 8 * TILE_STRIDE_B) =
                        __halves2half2(__float2half_rn(c[2]), __float2half_rn(c[3]));
                }
        }
    }

    // ---- Frobenius reduce -> g_fro ----
    #pragma unroll
    for (int o = 16; o; o >>= 1) fro += __shfl_xor_sync(0xFFFFFFFFu, fro, o);
    float* scr = (float*)(sm + XS_SCR);
    if (lane == 0) scr[w] = fro;
    __syncthreads();
    if (t == 0) {
        float s = 0.f;
        #pragma unroll
        for (int qq = 0; qq < 8; qq++) s += scr[qq];
        g_fro[mat * B_SZ + b] = s;
    }
}

// ---------------------------------------------------------------------------
// Kernel 2: 400-iteration PGD (as R7, plus: 5 register-resident k-bands,
// raw-copy init from g_G16, inline step, REDUX Newton count).
// ---------------------------------------------------------------------------
#define SM_WPRIV 0                               // 8 warps x 512 B private w
#define SM_Y1    4096                            // [2][256] f32 (double buffer)
#define SM_Y2    6144
#define SM_PROD  8192
#define SM_TILES 10240
#define SM_TOTAL (SM_TILES + BATCH_BYTES)        // 194560

__global__ __launch_bounds__(256, 1) void pgd_mma_kernel(const float* __restrict__ mu,
                                                         float* __restrict__ out) {
    extern __shared__ unsigned char sm[];
    const uint32_t smb = smem_u32(sm);
    const int b = blockIdx.x;
    const int t = threadIdx.x;
    const int lane = t & 31;
    const int r = t >> 5;                   // warp id == output band

    // ---- init: raw copy of both fp16 triangles (no conversion) ----
    {
        const uint4* src = (const uint4*)(g_G16 + (size_t)b * BATCH_BYTES);
        uint4* dst = (uint4*)(sm + SM_TILES);
        #pragma unroll 4
        for (int i = t; i < BATCH_BYTES / 16; i += 256) dst[i] = src[i];
    }

    const uint32_t t1base = smb + SM_TILES;
    const uint32_t t2base = smb + SM_TILES + MAT_BYTES;
    const uint32_t wpriv = smb + SM_WPRIV + (uint32_t)r * 512;

    const uint32_t lane_nt = (uint32_t)((lane & 7) + (lane & 8)) * TILE_STRIDE_B
                           + (uint32_t)((lane & 16) >> 1) * 2;
    const uint32_t lane_tr = (uint32_t)((lane & 7) + ((lane & 16) >> 1)) * TILE_STRIDE_B
                           + (uint32_t)(lane & 8) * 2;

    const float step = 1.0f / (LAMBD * g_fro[b] + KAPPA * sqrtf(g_fro[B_SZ + b]) + 1.0f);

    __syncthreads();

    // ---- preload k-bands 0..4 A-fragments into registers (160 regs) ----
    uint32_t fr[2][5][2][2][4];
    #pragma unroll
    for (int m = 0; m < 2; m++) {
        const uint32_t tb = m ? t2base : t1base;
        #pragma unroll
        for (int bb = 0; bb < 5; bb++) {
            const bool tr = (bb < r);
            const int aa = tr ? bb : r;
            const int bn = tr ? r : bb;
            const uint32_t tile = tb + (uint32_t)tri_idx(aa, bn) * TILE_BYTES;
            #pragma unroll
            for (int ks = 0; ks < 2; ks++) {
                if (tr) {
                    const uint32_t o = (uint32_t)ks * (16 * TILE_STRIDE_B) + lane_tr;
                    ldsm4t(fr[m][bb][ks][0][0], fr[m][bb][ks][0][1],
                           fr[m][bb][ks][0][2], fr[m][bb][ks][0][3], tile + o);
                    ldsm4t(fr[m][bb][ks][1][0], fr[m][bb][ks][1][1],
                           fr[m][bb][ks][1][2], fr[m][bb][ks][1][3], tile + o + 32);
                } else {
                    const uint32_t o = (uint32_t)ks * 32 + lane_nt;
                    ldsm4(fr[m][bb][ks][0][0], fr[m][bb][ks][0][1],
                          fr[m][bb][ks][0][2], fr[m][bb][ks][0][3], tile + o);
                    ldsm4(fr[m][bb][ks][1][0], fr[m][bb][ks][1][1],
                          fr[m][bb][ks][1][2], fr[m][bb][ks][1][3],
                          tile + o + 16 * TILE_STRIDE_B);
                }
            }
        }
    }

    // ---- replicated solver state (identical in every warp) ----
    float wv[8], mu_r[8];
    float tau = 0.0f;
    #pragma unroll
    for (int k = 0; k < 8; k++) {
        wv[k] = 1.0f / (float)N_SZ;
        mu_r[k] = mu[(size_t)b * N_SZ + lane + (k << 5)];
        const __half h = __float2half_rn(wv[k]);
        asm volatile("st.shared.u16 [%0], %1;"
                     :: "r"(wpriv + (uint32_t)(lane + (k << 5)) * 2),
                        "h"(__half_as_ushort(h)) : "memory");
    }
    __syncwarp();
    __syncthreads();

    #pragma unroll 1
    for (int it = 0; it < N_ITERS; it++) {
        const uint32_t buf = (uint32_t)(it & 1);
        float* const y1s = (float*)(sm + SM_Y1 + buf * 1024);
        float* const y2s = (float*)(sm + SM_Y2 + buf * 1024);
        float* const prods = (float*)(sm + SM_PROD + buf * 32);

        float c1A[4] = {0.f,0.f,0.f,0.f}, c1B[4] = {0.f,0.f,0.f,0.f};
        float c2A[4] = {0.f,0.f,0.f,0.f}, c2B[4] = {0.f,0.f,0.f,0.f};

        // ---- k-bands 0..4: register-resident fragments ----
        #pragma unroll
        for (int bb = 0; bb < 5; bb++) {
            #pragma unroll
            for (int ks = 0; ks < 2; ks++) {
                uint32_t b0, b1;
                const uint32_t waddr = wpriv + (uint32_t)(bb * 64 + ks * 32)
                                     + (uint32_t)(lane & 3) * 4;
                asm volatile("ld.shared.b32 %0, [%1];" : "=r"(b0) : "r"(waddr));
                asm volatile("ld.shared.b32 %0, [%1];" : "=r"(b1) : "r"(waddr + 16));
                if (lane >= 4) { b0 = 0u; b1 = 0u; }

                mma16816(c1A, fr[0][bb][ks][0][0], fr[0][bb][ks][0][1],
                              fr[0][bb][ks][0][2], fr[0][bb][ks][0][3], b0, b1);
                mma16816(c1B, fr[0][bb][ks][1][0], fr[0][bb][ks][1][1],
                              fr[0][bb][ks][1][2], fr[0][bb][ks][1][3], b0, b1);
                mma16816(c2A, fr[1][bb][ks][0][0], fr[1][bb][ks][0][1],
                              fr[1][bb][ks][0][2], fr[1][bb][ks][0][3], b0, b1);
                mma16816(c2B, fr[1][bb][ks][1][0], fr[1][bb][ks][1][1],
                              fr[1][bb][ks][1][2], fr[1][bb][ks][1][3], b0, b1);
            }
        }

        // ---- k-bands 5..7: streamed from SMEM via ldmatrix ----
        #pragma unroll
        for (int bb = 5; bb < 8; bb++) {
            const bool tr = (bb < r);
            const int aa = tr ? bb : r;
            const int bn = tr ? r : bb;
            const uint32_t toff = (uint32_t)tri_idx(aa, bn) * TILE_BYTES;
            const uint32_t tile1 = t1base + toff;
            const uint32_t tile2 = t2base + toff;
            #pragma unroll
            for (int ks = 0; ks < 2; ks++) {
                uint32_t b0, b1;
                const uint32_t waddr = wpriv + (uint32_t)(bb * 64 + ks * 32)
                                     + (uint32_t)(lane & 3) * 4;
                asm volatile("ld.shared.b32 %0, [%1];" : "=r"(b0) : "r"(waddr));
                asm volatile("ld.shared.b32 %0, [%1];" : "=r"(b1) : "r"(waddr + 16));
                if (lane >= 4) { b0 = 0u; b1 = 0u; }

                uint32_t a0, a1, a2, a3;
                if (tr) {
                    const uint32_t o = (uint32_t)ks * (16 * TILE_STRIDE_B) + lane_tr;
                    ldsm4t(a0, a1, a2, a3, tile1 + o);
                    mma16816(c1A, a0, a1, a2, a3, b0, b1);
                    ldsm4t(a0, a1, a2, a3, tile1 + o + 32);
                    mma16816(c1B, a0, a1, a2, a3, b0, b1);
                    ldsm4t(a0, a1, a2, a3, tile2 + o);
                    mma16816(c2A, a0, a1, a2, a3, b0, b1);
                    ldsm4t(a0, a1, a2, a3, tile2 + o + 32);
                    mma16816(c2B, a0, a1, a2, a3, b0, b1);
                } else {
                    const uint32_t o = (uint32_t)ks * 32 + lane_nt;
                    ldsm4(a0, a1, a2, a3, tile1 + o);
                    mma16816(c1A, a0, a1, a2, a3, b0, b1);
                    ldsm4(a0, a1, a2, a3, tile1 + o + 16 * TILE_STRIDE_B);
                    mma16816(c1B, a0, a1, a2, a3, b0, b1);
                    ldsm4(a0, a1, a2, a3, tile2 + o);
                    mma16816(c2A, a0, a1, a2, a3, b0, b1);
                    ldsm4(a0, a1, a2, a3, tile2 + o + 16 * TILE_STRIDE_B);
                    mma16816(c2B, a0, a1, a2, a3, b0, b1);
                }
            }
        }

        // ---- store y bands + fused prod partial ----
        const int g = lane >> 2;
        if ((lane & 3) == 0) {
            y1s[32 * r + g]      = c1A[0];
            y1s[32 * r + 8 + g]  = c1A[2];
            y1s[32 * r + 16 + g] = c1B[0];
            y1s[32 * r + 24 + g] = c1B[2];
            y2s[32 * r + g]      = c2A[0];
            y2s[32 * r + 8 + g]  = c2A[2];
            y2s[32 * r + 16 + g] = c2B[0];
            y2s[32 * r + 24 + g] = c2B[2];
        }
        {
            const float wg0 = __shfl_sync(0xFFFFFFFFu, wv[r], g);
            const float wg1 = __shfl_sync(0xFFFFFFFFu, wv[r], g + 8);
            const float wg2 = __shfl_sync(0xFFFFFFFFu, wv[r], g + 16);
            const float wg3 = __shfl_sync(0xFFFFFFFFu, wv[r], g + 24);
            float p = c2A[0] * wg0 + c2A[2] * wg1 + c2B[0] * wg2 + c2B[2] * wg3;
            p += __shfl_xor_sync(0xFFFFFFFFu, p, 4);
            p += __shfl_xor_sync(0xFFFFFFFFu, p, 8);
            p += __shfl_xor_sync(0xFFFFFFFFu, p, 16);
            if (lane == 0) prods[r] = p;
        }
        __syncthreads();   // the ONLY barrier per iteration

        // ---- replicated projection ----
        float pr = 0.f;
        #pragma unroll
        for (int q = 0; q < 8; q++) pr += prods[q];
        const float nrm = sqrtf(fmaxf(pr, 1e-12f));
        const float kin = KAPPA / nrm;

        float v[8];
        #pragma unroll
        for (int k = 0; k < 8; k++) {
            const int c = lane + (k << 5);
            const float grad = -mu_r[k] + LAMBD * y1s[c] + kin * y2s[c];
            v[k] = wv[k] - step * grad;
        }

        // Newton on f(tau) = sum(relu(v-tau)) - 1 (convex, pw-linear; warm
        // start never overshoots the root). cnt via hardware REDUX.
        float tt = tau;
        bool fb = false;
        for (int ni = 0; ni < 24; ni++) {
            float s = 0.f;
            int cnt = 0;
            #pragma unroll
            for (int k = 0; k < 8; k++) {
                const float d = v[k] - tt;
                if (d > 0.f) { s += d; cnt++; }
            }
            cnt = __reduce_add_sync(0xFFFFFFFFu, cnt);
            #pragma unroll
            for (int o = 16; o; o >>= 1)
                s += __shfl_xor_sync(0xFFFFFFFFu, s, o);
            if (cnt == 0) {
                if (fb) break;
                fb = true;
                float S = 0.f;
                #pragma unroll
                for (int k = 0; k < 8; k++) S += v[k];
                #pragma unroll
                for (int o = 16; o; o >>= 1)
                    S += __shfl_xor_sync(0xFFFFFFFFu, S, o);
                tt = (S - 1.0f) * (1.0f / (float)N_SZ);
                continue;
            }
            const float delta = (s - 1.0f) / (float)cnt;
            tt += delta;
            if (fabsf(delta) <= 1e-10f) break;
        }
        tau = tt;

        #pragma unroll
        for (int k = 0; k < 8; k++) {
            wv[k] = fmaxf(v[k] - tau, 0.f);
            const __half h = __float2half_rn(wv[k]);
            asm volatile("st.shared.u16 [%0], %1;"
                         :: "r"(wpriv + (uint32_t)(lane + (k << 5)) * 2),
                            "h"(__half_as_ushort(h)) : "memory");
        }
        __syncwarp();
    }

    // ---- final clamp + renormalize (warp 0 writes) ----
    if (r == 0) {
        float s = 0.f;
        #pragma unroll
        for (int k = 0; k < 8; k++) { wv[k] = fmaxf(wv[k], 0.f); s += wv[k]; }
        #pragma unroll
        for (int o = 16; o; o >>= 1) s += __shfl_xor_sync(0xFFFFFFFFu, s, o);
        const float inv = 1.0f / (s + 1e-12f);
        #pragma unroll
        for (int k = 0; k < 8; k++)
            out[(size_t)b * N_SZ + lane + (k << 5)] = wv[k] * inv;
    }
}

// ---------------------------------------------------------------------------
// Launcher
// ---------------------------------------------------------------------------
extern "C" void kernel_launch(void* const* d_in, const int* in_sizes, int n_in,
                              void* d_out, int out_size) {
    const float* mu = (const float*)d_in[0];
    const float* U  = (const float*)d_in[1];
    const float* A  = (const float*)d_in[2];
    float* out = (float*)d_out;

    cudaFuncSetAttribute(syrk16_kernel, cudaFuncAttributeMaxDynamicSharedMemorySize,
                         SYRK_SMEM);
    cudaFuncSetAttribute(pgd_mma_kernel, cudaFuncAttributeMaxDynamicSharedMemorySize,
                         SM_TOTAL);

    syrk16_kernel<<<2 * B_SZ, 256, SYRK_SMEM>>>(U, A);
    pgd_mma_kernel<<<B_SZ, 256, SM_TOTAL>>>(mu, out);
}